// round 8
// baseline (speedup 1.0000x reference)
#include <cuda_runtime.h>

#define NN 20000
#define NE 320000
#define LDIM 128
#define TILE 64
#define ASTR 132              // padded A-tile row stride (floats) -> bank de-phase
#define NT 256
#define NLAYERS 5

// -------- scratch (static device allocations; no runtime alloc) --------
__device__ float g_h[NN * LDIM];     // node features
__device__ float g_P[NN * LDIM];     // h @ W1a  (dst-side precontraction)
__device__ float g_Q[NN * LDIM];     // h @ W1b  (src-side precontraction)
__device__ float g_agg[NN * LDIM];   // segment sum accumulator
__device__ float g_e[NE * LDIM];     // encoded edge features (constant over layers)

typedef unsigned long long u64t;

// -------- packed fp32x2 primitives --------
__device__ __forceinline__ void ffma2(u64t& d, u64t a, u64t b) {
    asm("fma.rn.f32x2 %0, %1, %2, %0;" : "+l"(d) : "l"(a), "l"(b));
}
__device__ __forceinline__ u64t pack2(float x, float y) {
    u64t v; asm("mov.b64 %0, {%1, %2};" : "=l"(v) : "f"(x), "f"(y)); return v;
}
__device__ __forceinline__ float2 unpack2(u64t v) {
    float2 f; asm("mov.b64 {%0, %1}, %2;" : "=f"(f.x), "=f"(f.y) : "l"(v)); return f;
}
__device__ __forceinline__ float prelu1(float v, float a) { return v > 0.f ? v : a * v; }

__device__ __forceinline__ void red_add_v4(float* addr, float4 v) {
    asm volatile("red.global.add.v4.f32 [%0], {%1,%2,%3,%4};"
                 :: "l"(addr), "f"(v.x), "f"(v.y), "f"(v.z), "f"(v.w)
                 : "memory");
}

// -------- smem fills --------
__device__ __forceinline__ void cp_f4(float* dst, const float* __restrict__ src,
                                      int n, int tid) {
    for (int i = tid * 4; i < n; i += NT * 4)
        *(float4*)(dst + i) = *(const float4*)(src + i);
}

// 64x128 row tile from [nrows,128] (clamped rows) into padded-stride As[64][ASTR]
__device__ __forceinline__ void fill_rows(float* As, const float* __restrict__ src,
                                          int r0, int nrows, int tid) {
    for (int i = tid * 4; i < TILE * LDIM; i += NT * 4) {
        int r = i >> 7;
        int k = i & (LDIM - 1);
        int gr = r0 + r; if (gr >= nrows) gr = nrows - 1;
        *(float4*)(As + r * ASTR + k) = *(const float4*)(src + (size_t)gr * LDIM + k);
    }
}

// -------- core packed GEMM (column-paired accumulators) --------
// Warp covers 8 rows. Lane: lx = lane&15 -> cols lx*8..+7, ly = lane>>4 -> 4-row half.
// acc[r][j] f32x2 = outputs (row_base+r, c0+2j),(row_base+r, c0+2j+1), r<4.
// As row-major [64][AS], Ws row-major [K][128]. K multiple of 4.
template<int K, int AS>
__device__ __forceinline__ void gemm_cp(const float* __restrict__ As,
                                        const float* __restrict__ Ws,
                                        int row_base, int c0, u64t acc[4][4]) {
#pragma unroll 2
    for (int k = 0; k < K; k += 4) {
        float4 av[4];
#pragma unroll
        for (int r = 0; r < 4; ++r)
            av[r] = *(const float4*)(As + (row_base + r) * AS + k);
#pragma unroll
        for (int kk = 0; kk < 4; ++kk) {
            const float* wr = Ws + (k + kk) * LDIM + c0;
            ulonglong2 w0 = *(const ulonglong2*)(wr);
            ulonglong2 w1 = *(const ulonglong2*)(wr + 4);
#pragma unroll
            for (int r = 0; r < 4; ++r) {
                float a = (kk == 0) ? av[r].x : (kk == 1) ? av[r].y
                        : (kk == 2) ? av[r].z : av[r].w;
                u64t ad = pack2(a, a);
                ffma2(acc[r][0], ad, w0.x);
                ffma2(acc[r][1], ad, w0.y);
                ffma2(acc[r][2], ad, w1.x);
                ffma2(acc[r][3], ad, w1.y);
            }
        }
    }
}

__device__ __forceinline__ void acc_initb(u64t acc[4][4], const float* __restrict__ b, int c0) {
    ulonglong2 b0 = *(const ulonglong2*)(b + c0);
    ulonglong2 b1 = *(const ulonglong2*)(b + c0 + 4);
#pragma unroll
    for (int r = 0; r < 4; ++r) {
        acc[r][0] = b0.x; acc[r][1] = b0.y; acc[r][2] = b1.x; acc[r][3] = b1.y;
    }
}
__device__ __forceinline__ void acc_init0(u64t acc[4][4]) {
#pragma unroll
    for (int r = 0; r < 4; ++r)
        acc[r][0] = acc[r][1] = acc[r][2] = acc[r][3] = 0ull;
}
__device__ __forceinline__ void acc_fin2(const u64t a[4], float4& lo, float4& hi) {
    float2 f0 = unpack2(a[0]), f1 = unpack2(a[1]), f2 = unpack2(a[2]), f3 = unpack2(a[3]);
    lo = make_float4(f0.x, f0.y, f1.x, f1.y);
    hi = make_float4(f2.x, f2.y, f3.x, f3.y);
}

// prelu(acc) -> U (padded stride ASTR)
__device__ __forceinline__ void store_U(float* U, u64t acc[4][4],
                                        int row_base, int c0, float al) {
#pragma unroll
    for (int r = 0; r < 4; ++r) {
        float4 lo, hi; acc_fin2(acc[r], lo, hi);
        lo.x = prelu1(lo.x, al); lo.y = prelu1(lo.y, al);
        lo.z = prelu1(lo.z, al); lo.w = prelu1(lo.w, al);
        hi.x = prelu1(hi.x, al); hi.y = prelu1(hi.y, al);
        hi.z = prelu1(hi.z, al); hi.w = prelu1(hi.w, al);
        float* p = U + (row_base + r) * ASTR + c0;
        *(float4*)(p)     = lo;
        *(float4*)(p + 4) = hi;
    }
}

// thread -> (row_base, c0): warp wy covers rows wy*8..+7; ly half of 4 rows; lx -> 8 cols
__device__ __forceinline__ void tmap(int tid, int& row_base, int& c0) {
    int wy = tid >> 5;
    int lane = tid & 31;
    row_base = wy * 8 + (lane >> 4) * 4;
    c0 = (lane & 15) * 8;
}

// ============================ encoder (node / edge) ============================
// K1P: padded K (stride + W rows); chosen so 4-row groups de-phase banks where it matters
template<int K1, int K1P>
__global__ __launch_bounds__(NT, 2)
void encoder_kernel(const float* __restrict__ in,
                    const float* __restrict__ w1, const float* __restrict__ b1,
                    const float* __restrict__ aslope,
                    const float* __restrict__ w2, const float* __restrict__ b2,
                    float* __restrict__ out, int nrows) {
    extern __shared__ float sm[];
    float* Ws = sm;                      // [<=128][128]
    float* As = sm + LDIM * LDIM;        // [64][K1P] then U [64][ASTR]
    int tid = threadIdx.x;
    int row_base, c0; tmap(tid, row_base, c0);
    int r0 = blockIdx.x * TILE;

    for (int i = tid; i < TILE * K1P; i += NT) {
        int r = i / K1P, k = i - r * K1P;
        int gr = r0 + r; if (gr >= nrows) gr = nrows - 1;
        As[i] = (k < K1) ? in[(size_t)gr * K1 + k] : 0.f;
    }
    for (int i = tid; i < K1P * LDIM; i += NT)
        Ws[i] = (i < K1 * LDIM) ? w1[i] : 0.f;
    __syncthreads();

    u64t acc[4][4];
    acc_initb(acc, b1, c0);
    gemm_cp<K1P, K1P>(As, Ws, row_base, c0, acc);

    float al = *aslope;
    __syncthreads();
    store_U(As, acc, row_base, c0, al);
    cp_f4(Ws, w2, LDIM * LDIM, tid);
    __syncthreads();

    acc_initb(acc, b2, c0);
    gemm_cp<LDIM, ASTR>(As, Ws, row_base, c0, acc);

#pragma unroll
    for (int r = 0; r < 4; ++r) {
        int gr = r0 + row_base + r;
        if (gr < nrows) {
            float4 lo, hi; acc_fin2(acc[r], lo, hi);
            *(float4*)(out + (size_t)gr * LDIM + c0)     = lo;
            *(float4*)(out + (size_t)gr * LDIM + c0 + 4) = hi;
        }
    }
}

// ============================ per-layer: P/Q + zero agg ============================
__global__ __launch_bounds__(NT, 2)
void pq_kernel(const float* __restrict__ wl /* le_w1 layer base [384,128] */) {
    extern __shared__ float sm[];
    float* Ws = sm;
    float* As = sm + LDIM * LDIM;
    int tid = threadIdx.x;
    int row_base, c0; tmap(tid, row_base, c0);
    int r0 = blockIdx.x * TILE;

    fill_rows(As, g_h, r0, NN, tid);
    cp_f4(Ws, wl, LDIM * LDIM, tid);                 // W1a (dst side)
    __syncthreads();

    float4 z = make_float4(0.f, 0.f, 0.f, 0.f);
    u64t acc[4][4];
    acc_init0(acc);
    gemm_cp<LDIM, ASTR>(As, Ws, row_base, c0, acc);
#pragma unroll
    for (int r = 0; r < 4; ++r) {
        int gr = r0 + row_base + r;
        if (gr < NN) {
            float4 lo, hi; acc_fin2(acc[r], lo, hi);
            *(float4*)(g_P + (size_t)gr * LDIM + c0)       = lo;
            *(float4*)(g_P + (size_t)gr * LDIM + c0 + 4)   = hi;
            *(float4*)(g_agg + (size_t)gr * LDIM + c0)     = z;
            *(float4*)(g_agg + (size_t)gr * LDIM + c0 + 4) = z;
        }
    }
    __syncthreads();
    cp_f4(Ws, wl + LDIM * LDIM, LDIM * LDIM, tid);   // W1b (src side)
    __syncthreads();
    acc_init0(acc);
    gemm_cp<LDIM, ASTR>(As, Ws, row_base, c0, acc);
#pragma unroll
    for (int r = 0; r < 4; ++r) {
        int gr = r0 + row_base + r;
        if (gr < NN) {
            float4 lo, hi; acc_fin2(acc[r], lo, hi);
            *(float4*)(g_Q + (size_t)gr * LDIM + c0)     = lo;
            *(float4*)(g_Q + (size_t)gr * LDIM + c0 + 4) = hi;
        }
    }
}

// ============================ per-layer: edge messages + scatter ============================
__global__ __launch_bounds__(NT, 2)
void edge_kernel(const int* __restrict__ eidx,
                 const float* __restrict__ wl,    // le_w1 layer base [384,128]
                 const float* __restrict__ b1, const float* __restrict__ aslope,
                 const float* __restrict__ w2, const float* __restrict__ b2) {
    extern __shared__ float sm[];
    float* Ws = sm;
    float* As = sm + LDIM * LDIM;
    int* sdst = (int*)(As + TILE * ASTR);
    int* ssrc = sdst + TILE;
    int tid = threadIdx.x;
    int row_base, c0; tmap(tid, row_base, c0);
    size_t e0 = (size_t)blockIdx.x * TILE;

    fill_rows(As, g_e + e0 * LDIM, 0, TILE, tid);    // e tile (contiguous rows)
    cp_f4(Ws, wl + 256 * LDIM, LDIM * LDIM, tid);    // W1c (e side)
    if (tid < TILE) {
        ssrc[tid] = eidx[e0 + tid];        // edge_index[0] = src (x_j)
        sdst[tid] = eidx[NE + e0 + tid];   // edge_index[1] = dst (x_i / agg idx)
    }
    __syncthreads();

    float4 ba = *(const float4*)(b1 + c0);
    float4 bb = *(const float4*)(b1 + c0 + 4);
    u64t acc[4][4];
#pragma unroll
    for (int r = 0; r < 4; ++r) {
        int d = sdst[row_base + r];
        int s = ssrc[row_base + r];
        float4 Pa = *(const float4*)(g_P + (size_t)d * LDIM + c0);
        float4 Pb = *(const float4*)(g_P + (size_t)d * LDIM + c0 + 4);
        float4 Qa = *(const float4*)(g_Q + (size_t)s * LDIM + c0);
        float4 Qb = *(const float4*)(g_Q + (size_t)s * LDIM + c0 + 4);
        acc[r][0] = pack2(ba.x + Pa.x + Qa.x, ba.y + Pa.y + Qa.y);
        acc[r][1] = pack2(ba.z + Pa.z + Qa.z, ba.w + Pa.w + Qa.w);
        acc[r][2] = pack2(bb.x + Pb.x + Qb.x, bb.y + Pb.y + Qb.y);
        acc[r][3] = pack2(bb.z + Pb.z + Qb.z, bb.w + Pb.w + Qb.w);
    }
    gemm_cp<LDIM, ASTR>(As, Ws, row_base, c0, acc);

    float al = *aslope;
    __syncthreads();
    store_U(As, acc, row_base, c0, al);
    cp_f4(Ws, w2, LDIM * LDIM, tid);
    __syncthreads();

    acc_initb(acc, b2, c0);
    gemm_cp<LDIM, ASTR>(As, Ws, row_base, c0, acc);

    // scatter-add m into agg[dst] (m never materialized)
#pragma unroll
    for (int r = 0; r < 4; ++r) {
        int d = sdst[row_base + r];
        float4 lo, hi; acc_fin2(acc[r], lo, hi);
        red_add_v4(g_agg + (size_t)d * LDIM + c0, lo);
        red_add_v4(g_agg + (size_t)d * LDIM + c0 + 4, hi);
    }
}

// ============================ per-layer: node update ============================
__global__ __launch_bounds__(NT, 2)
void node_kernel(const float* __restrict__ wn1,  // ln_w1 layer base [256,128]
                 const float* __restrict__ b1, const float* __restrict__ aslope,
                 const float* __restrict__ w2, const float* __restrict__ b2) {
    extern __shared__ float sm[];
    float* Ws = sm;
    float* As = sm + LDIM * LDIM;
    int tid = threadIdx.x;
    int row_base, c0; tmap(tid, row_base, c0);
    int r0 = blockIdx.x * TILE;

    fill_rows(As, g_h, r0, NN, tid);
    cp_f4(Ws, wn1, LDIM * LDIM, tid);          // rows 0..127 (h side)
    __syncthreads();

    u64t acc[4][4];
    acc_initb(acc, b1, c0);
    gemm_cp<LDIM, ASTR>(As, Ws, row_base, c0, acc);

    __syncthreads();
    fill_rows(As, g_agg, r0, NN, tid);
    cp_f4(Ws, wn1 + LDIM * LDIM, LDIM * LDIM, tid);   // rows 128..255 (agg side)
    __syncthreads();
    gemm_cp<LDIM, ASTR>(As, Ws, row_base, c0, acc);    // accumulate

    float al = *aslope;
    __syncthreads();
    store_U(As, acc, row_base, c0, al);
    cp_f4(Ws, w2, LDIM * LDIM, tid);
    __syncthreads();

    acc_initb(acc, b2, c0);
    gemm_cp<LDIM, ASTR>(As, Ws, row_base, c0, acc);

#pragma unroll
    for (int r = 0; r < 4; ++r) {
        int gr = r0 + row_base + r;
        if (gr < NN) {
            float4 lo, hi; acc_fin2(acc[r], lo, hi);
            float* hp = g_h + (size_t)gr * LDIM + c0;
            float4 h0 = *(float4*)(hp);
            float4 h1 = *(float4*)(hp + 4);
            h0.x += lo.x; h0.y += lo.y; h0.z += lo.z; h0.w += lo.w;
            h1.x += hi.x; h1.y += hi.y; h1.z += hi.z; h1.w += hi.w;
            *(float4*)(hp)     = h0;                       // h = h + upd
            *(float4*)(hp + 4) = h1;
        }
    }
}

// ============================ decoder ============================
__global__ __launch_bounds__(NT, 2)
void dec_kernel(const float* __restrict__ w1, const float* __restrict__ b1,
                const float* __restrict__ aslope,
                const float* __restrict__ w2, const float* __restrict__ b2,
                float* __restrict__ out) {
    extern __shared__ float sm[];
    float* Ws = sm;
    float* As = sm + LDIM * LDIM;
    int tid = threadIdx.x;
    int row_base, c0; tmap(tid, row_base, c0);
    int r0 = blockIdx.x * TILE;

    fill_rows(As, g_h, r0, NN, tid);
    cp_f4(Ws, w1, LDIM * LDIM, tid);
    __syncthreads();

    u64t acc[4][4];
    acc_initb(acc, b1, c0);
    gemm_cp<LDIM, ASTR>(As, Ws, row_base, c0, acc);

    float al = *aslope;
    __syncthreads();
    store_U(As, acc, row_base, c0, al);
    __syncthreads();

    for (int idx = tid; idx < TILE * 3; idx += NT) {
        int r = idx / 3, c = idx - r * 3;
        int gr = r0 + r;
        if (gr < NN) {
            float s = b2[c];
#pragma unroll 8
            for (int k = 0; k < LDIM; ++k)
                s = fmaf(As[r * ASTR + k], w2[k * 3 + c], s);
            out[(size_t)gr * 3 + c] = s;
        }
    }
}

// ============================ host ============================
extern "C" void kernel_launch(void* const* d_in, const int* in_sizes, int n_in,
                              void* d_out, int out_size) {
    const float* x          = (const float*)d_in[0];
    const float* edge_attr  = (const float*)d_in[1];
    const int*   edge_index = (const int*)  d_in[2];
    const float* ne_w1 = (const float*)d_in[3];
    const float* ne_b1 = (const float*)d_in[4];
    const float* ne_a  = (const float*)d_in[5];
    const float* ne_w2 = (const float*)d_in[6];
    const float* ne_b2 = (const float*)d_in[7];
    const float* ee_w1 = (const float*)d_in[8];
    const float* ee_b1 = (const float*)d_in[9];
    const float* ee_a  = (const float*)d_in[10];
    const float* ee_w2 = (const float*)d_in[11];
    const float* ee_b2 = (const float*)d_in[12];
    const float* le_w1 = (const float*)d_in[13];
    const float* le_b1 = (const float*)d_in[14];
    const float* le_a  = (const float*)d_in[15];
    const float* le_w2 = (const float*)d_in[16];
    const float* le_b2 = (const float*)d_in[17];
    const float* ln_w1 = (const float*)d_in[18];
    const float* ln_b1 = (const float*)d_in[19];
    const float* ln_a  = (const float*)d_in[20];
    const float* ln_w2 = (const float*)d_in[21];
    const float* ln_b2 = (const float*)d_in[22];
    const float* de_w1 = (const float*)d_in[23];
    const float* de_b1 = (const float*)d_in[24];
    const float* de_a  = (const float*)d_in[25];
    const float* de_w2 = (const float*)d_in[26];
    const float* de_b2 = (const float*)d_in[27];
    float* out = (float*)d_out;

    float *p_h = nullptr, *p_e = nullptr;
    cudaGetSymbolAddress((void**)&p_h, g_h);
    cudaGetSymbolAddress((void**)&p_e, g_e);

    const int SMEM_MAIN = (LDIM * LDIM + TILE * ASTR) * 4;   // ~97 KB
    const int SMEM_EDGE = SMEM_MAIN + 2 * TILE * 4;          // + index staging

    cudaFuncSetAttribute((const void*)encoder_kernel<30,36>, cudaFuncAttributeMaxDynamicSharedMemorySize, SMEM_MAIN);
    cudaFuncSetAttribute((const void*)encoder_kernel<4,4>,   cudaFuncAttributeMaxDynamicSharedMemorySize, SMEM_MAIN);
    cudaFuncSetAttribute((const void*)pq_kernel,   cudaFuncAttributeMaxDynamicSharedMemorySize, SMEM_MAIN);
    cudaFuncSetAttribute((const void*)edge_kernel, cudaFuncAttributeMaxDynamicSharedMemorySize, SMEM_EDGE);
    cudaFuncSetAttribute((const void*)node_kernel, cudaFuncAttributeMaxDynamicSharedMemorySize, SMEM_MAIN);
    cudaFuncSetAttribute((const void*)dec_kernel,  cudaFuncAttributeMaxDynamicSharedMemorySize, SMEM_MAIN);

    const int nb_n = (NN + TILE - 1) / TILE;   // 313
    const int nb_e = NE / TILE;                // 5000

    encoder_kernel<30,36><<<nb_n, NT, SMEM_MAIN>>>(x, ne_w1, ne_b1, ne_a, ne_w2, ne_b2, p_h, NN);
    encoder_kernel<4,4>  <<<nb_e, NT, SMEM_MAIN>>>(edge_attr, ee_w1, ee_b1, ee_a, ee_w2, ee_b2, p_e, NE);

    for (int l = 0; l < NLAYERS; ++l) {
        const float* wl = le_w1 + (size_t)l * 384 * LDIM;
        pq_kernel<<<nb_n, NT, SMEM_MAIN>>>(wl);
        edge_kernel<<<nb_e, NT, SMEM_EDGE>>>(edge_index, wl,
                                             le_b1 + l * LDIM, le_a + l,
                                             le_w2 + (size_t)l * LDIM * LDIM,
                                             le_b2 + l * LDIM);
        node_kernel<<<nb_n, NT, SMEM_MAIN>>>(ln_w1 + (size_t)l * 256 * LDIM,
                                             ln_b1 + l * LDIM, ln_a + l,
                                             ln_w2 + (size_t)l * LDIM * LDIM,
                                             ln_b2 + l * LDIM);
    }
    dec_kernel<<<nb_n, NT, SMEM_MAIN>>>(de_w1, de_b1, de_a, de_w2, de_b2, out);
}

// round 9
// speedup vs baseline: 1.4694x; 1.4694x over previous
#include <cuda_runtime.h>

#define NN 20000
#define NE 320000
#define LDIM 128
#define TILE 128              // rows per CTA
#define ASTR 132              // padded A/U row stride (floats)
#define NT 256
#define KH 64                 // k-half staged in smem
#define NLAYERS 5

// -------- scratch (static device allocations; no runtime alloc) --------
__device__ float g_h[NN * LDIM];     // node features
__device__ float g_P[NN * LDIM];     // h @ W1a  (dst-side precontraction)
__device__ float g_Q[NN * LDIM];     // h @ W1b  (src-side precontraction)
__device__ float g_agg[NN * LDIM];   // segment sum accumulator
__device__ float g_e[NE * LDIM];     // encoded edge features (constant over layers)

typedef unsigned long long u64t;

// -------- packed fp32x2 primitives --------
__device__ __forceinline__ void ffma2(u64t& d, u64t a, u64t b) {
    asm("fma.rn.f32x2 %0, %1, %2, %0;" : "+l"(d) : "l"(a), "l"(b));
}
__device__ __forceinline__ u64t pack2(float x, float y) {
    u64t v; asm("mov.b64 %0, {%1, %2};" : "=l"(v) : "f"(x), "f"(y)); return v;
}
__device__ __forceinline__ float2 unpack2(u64t v) {
    float2 f; asm("mov.b64 {%0, %1}, %2;" : "=f"(f.x), "=f"(f.y) : "l"(v)); return f;
}
__device__ __forceinline__ float prelu1(float v, float a) { return v > 0.f ? v : a * v; }

__device__ __forceinline__ void red_add_v4(float* addr, float4 v) {
    asm volatile("red.global.add.v4.f32 [%0], {%1,%2,%3,%4};"
                 :: "l"(addr), "f"(v.x), "f"(v.y), "f"(v.z), "f"(v.w)
                 : "memory");
}

// -------- smem fills --------
__device__ __forceinline__ void cp_f4(float* dst, const float* __restrict__ src,
                                      int n, int tid) {
    for (int i = tid * 4; i < n; i += NT * 4)
        *(float4*)(dst + i) = *(const float4*)(src + i);
}

// TILE x 128 row tile from [nrows,128] (clamped rows) into padded As[TILE][ASTR]
__device__ __forceinline__ void fill_rows(float* As, const float* __restrict__ src,
                                          int r0, int nrows, int tid) {
    for (int i = tid * 4; i < TILE * LDIM; i += NT * 4) {
        int r = i >> 7;
        int k = i & (LDIM - 1);
        int gr = r0 + r; if (gr >= nrows) gr = nrows - 1;
        *(float4*)(As + r * ASTR + k) = *(const float4*)(src + (size_t)gr * LDIM + k);
    }
}

// -------- core packed GEMM (column-paired accumulators, 16 rows/warp) --------
// Warp covers 16 rows (2 x 8-row halves via ly). Each thread: 8 rows x 8 cols.
// acc[r][j] f32x2 = outputs (row_base+r, c0+2j),(row_base+r, c0+2j+1).
// As already offset to k-start column; Ws holds K rows of [128] cols.
template<int K, int AS>
__device__ __forceinline__ void gemm_cp(const float* __restrict__ As,
                                        const float* __restrict__ Ws,
                                        int row_base, int c0, u64t acc[8][4]) {
#pragma unroll 2
    for (int k = 0; k < K; k += 4) {
        float4 av[8];
#pragma unroll
        for (int r = 0; r < 8; ++r)
            av[r] = *(const float4*)(As + (row_base + r) * AS + k);
#pragma unroll
        for (int kk = 0; kk < 4; ++kk) {
            const float* wr = Ws + (k + kk) * LDIM + c0;
            ulonglong2 w0 = *(const ulonglong2*)(wr);
            ulonglong2 w1 = *(const ulonglong2*)(wr + 4);
#pragma unroll
            for (int r = 0; r < 8; ++r) {
                float a = (kk == 0) ? av[r].x : (kk == 1) ? av[r].y
                        : (kk == 2) ? av[r].z : av[r].w;
                u64t ad = pack2(a, a);
                ffma2(acc[r][0], ad, w0.x);
                ffma2(acc[r][1], ad, w0.y);
                ffma2(acc[r][2], ad, w1.x);
                ffma2(acc[r][3], ad, w1.y);
            }
        }
    }
}

__device__ __forceinline__ void acc_initb(u64t acc[8][4], const float* __restrict__ b, int c0) {
    ulonglong2 b0 = *(const ulonglong2*)(b + c0);
    ulonglong2 b1 = *(const ulonglong2*)(b + c0 + 4);
#pragma unroll
    for (int r = 0; r < 8; ++r) {
        acc[r][0] = b0.x; acc[r][1] = b0.y; acc[r][2] = b1.x; acc[r][3] = b1.y;
    }
}
__device__ __forceinline__ void acc_init0(u64t acc[8][4]) {
#pragma unroll
    for (int r = 0; r < 8; ++r)
        acc[r][0] = acc[r][1] = acc[r][2] = acc[r][3] = 0ull;
}
__device__ __forceinline__ void acc_fin2(const u64t a[4], float4& lo, float4& hi) {
    float2 f0 = unpack2(a[0]), f1 = unpack2(a[1]), f2 = unpack2(a[2]), f3 = unpack2(a[3]);
    lo = make_float4(f0.x, f0.y, f1.x, f1.y);
    hi = make_float4(f2.x, f2.y, f3.x, f3.y);
}

// prelu(acc) -> U (padded stride ASTR)
__device__ __forceinline__ void store_U(float* U, u64t acc[8][4],
                                        int row_base, int c0, float al) {
#pragma unroll
    for (int r = 0; r < 8; ++r) {
        float4 lo, hi; acc_fin2(acc[r], lo, hi);
        lo.x = prelu1(lo.x, al); lo.y = prelu1(lo.y, al);
        lo.z = prelu1(lo.z, al); lo.w = prelu1(lo.w, al);
        hi.x = prelu1(hi.x, al); hi.y = prelu1(hi.y, al);
        hi.z = prelu1(hi.z, al); hi.w = prelu1(hi.w, al);
        float* p = U + (row_base + r) * ASTR + c0;
        *(float4*)(p)     = lo;
        *(float4*)(p + 4) = hi;
    }
}

// thread -> (row_base, c0): warp wy covers rows wy*16..+15 (ly: 8-row half), lx -> 8 cols
__device__ __forceinline__ void tmap(int tid, int& row_base, int& c0) {
    int wy = tid >> 5;
    int lane = tid & 31;
    row_base = wy * 16 + (lane >> 4) * 8;
    c0 = (lane & 15) * 8;
}

// shared layout: Ws [KH][128] (32KB), then As/U [TILE][ASTR]
#define WS_FLOATS (KH * LDIM)
#define SMEM_MAIN ((WS_FLOATS + TILE * ASTR) * 4)
#define SMEM_EDGE (SMEM_MAIN + 2 * TILE * 4)

// ============================ encoder (node / edge) ============================
// K1P <= KH: single-stage first GEMM; second GEMM (K=128) in two halves.
template<int K1, int K1P>
__global__ __launch_bounds__(NT, 2)
void encoder_kernel(const float* __restrict__ in,
                    const float* __restrict__ w1, const float* __restrict__ b1,
                    const float* __restrict__ aslope,
                    const float* __restrict__ w2, const float* __restrict__ b2,
                    float* __restrict__ out, int nrows) {
    extern __shared__ float sm[];
    float* Ws = sm;
    float* As = sm + WS_FLOATS;
    int tid = threadIdx.x;
    int row_base, c0; tmap(tid, row_base, c0);
    int r0 = blockIdx.x * TILE;

    // A tile [TILE][K1P], zero padded
    for (int i = tid; i < TILE * K1P; i += NT) {
        int r = i / K1P, k = i - r * K1P;
        int gr = r0 + r; if (gr >= nrows) gr = nrows - 1;
        As[i] = (k < K1) ? in[(size_t)gr * K1 + k] : 0.f;
    }
    for (int i = tid; i < K1P * LDIM; i += NT)
        Ws[i] = (i < K1 * LDIM) ? w1[i] : 0.f;
    __syncthreads();

    u64t acc[8][4];
    acc_initb(acc, b1, c0);
    gemm_cp<K1P, K1P>(As, Ws, row_base, c0, acc);

    float al = *aslope;
    __syncthreads();
    store_U(As, acc, row_base, c0, al);
    cp_f4(Ws, w2, WS_FLOATS, tid);
    __syncthreads();

    acc_initb(acc, b2, c0);
    gemm_cp<KH, ASTR>(As, Ws, row_base, c0, acc);
    __syncthreads();
    cp_f4(Ws, w2 + WS_FLOATS, WS_FLOATS, tid);
    __syncthreads();
    gemm_cp<KH, ASTR>(As + KH, Ws, row_base, c0, acc);

#pragma unroll
    for (int r = 0; r < 8; ++r) {
        int gr = r0 + row_base + r;
        if (gr < nrows) {
            float4 lo, hi; acc_fin2(acc[r], lo, hi);
            *(float4*)(out + (size_t)gr * LDIM + c0)     = lo;
            *(float4*)(out + (size_t)gr * LDIM + c0 + 4) = hi;
        }
    }
}

// ============================ per-layer: P/Q + zero agg ============================
__global__ __launch_bounds__(NT, 2)
void pq_kernel(const float* __restrict__ wl /* le_w1 layer base [384,128] */) {
    extern __shared__ float sm[];
    float* Ws = sm;
    float* As = sm + WS_FLOATS;
    int tid = threadIdx.x;
    int row_base, c0; tmap(tid, row_base, c0);
    int r0 = blockIdx.x * TILE;

    fill_rows(As, g_h, r0, NN, tid);
    cp_f4(Ws, wl, WS_FLOATS, tid);                    // W1a rows 0..63
    __syncthreads();

    float4 z = make_float4(0.f, 0.f, 0.f, 0.f);
    u64t acc[8][4];
    acc_init0(acc);
    gemm_cp<KH, ASTR>(As, Ws, row_base, c0, acc);
    __syncthreads();
    cp_f4(Ws, wl + WS_FLOATS, WS_FLOATS, tid);        // W1a rows 64..127
    __syncthreads();
    gemm_cp<KH, ASTR>(As + KH, Ws, row_base, c0, acc);
#pragma unroll
    for (int r = 0; r < 8; ++r) {
        int gr = r0 + row_base + r;
        if (gr < NN) {
            float4 lo, hi; acc_fin2(acc[r], lo, hi);
            *(float4*)(g_P + (size_t)gr * LDIM + c0)       = lo;
            *(float4*)(g_P + (size_t)gr * LDIM + c0 + 4)   = hi;
            *(float4*)(g_agg + (size_t)gr * LDIM + c0)     = z;
            *(float4*)(g_agg + (size_t)gr * LDIM + c0 + 4) = z;
        }
    }
    __syncthreads();
    cp_f4(Ws, wl + 2 * WS_FLOATS, WS_FLOATS, tid);    // W1b rows 0..63
    __syncthreads();
    acc_init0(acc);
    gemm_cp<KH, ASTR>(As, Ws, row_base, c0, acc);
    __syncthreads();
    cp_f4(Ws, wl + 3 * WS_FLOATS, WS_FLOATS, tid);    // W1b rows 64..127
    __syncthreads();
    gemm_cp<KH, ASTR>(As + KH, Ws, row_base, c0, acc);
#pragma unroll
    for (int r = 0; r < 8; ++r) {
        int gr = r0 + row_base + r;
        if (gr < NN) {
            float4 lo, hi; acc_fin2(acc[r], lo, hi);
            *(float4*)(g_Q + (size_t)gr * LDIM + c0)     = lo;
            *(float4*)(g_Q + (size_t)gr * LDIM + c0 + 4) = hi;
        }
    }
}

// ============================ per-layer: edge messages + scatter ============================
__global__ __launch_bounds__(NT, 2)
void edge_kernel(const int* __restrict__ eidx,
                 const float* __restrict__ wl,    // le_w1 layer base [384,128]
                 const float* __restrict__ b1, const float* __restrict__ aslope,
                 const float* __restrict__ w2, const float* __restrict__ b2) {
    extern __shared__ float sm[];
    float* Ws = sm;
    float* As = sm + WS_FLOATS;
    int* sdst = (int*)(As + TILE * ASTR);
    int* ssrc = sdst + TILE;
    int tid = threadIdx.x;
    int row_base, c0; tmap(tid, row_base, c0);
    size_t e0 = (size_t)blockIdx.x * TILE;

    fill_rows(As, g_e + e0 * LDIM, 0, TILE, tid);       // e tile (contiguous rows)
    cp_f4(Ws, wl + 256 * LDIM, WS_FLOATS, tid);          // W1c rows 0..63
    if (tid < TILE) {
        ssrc[tid] = eidx[e0 + tid];        // edge_index[0] = src (x_j)
        sdst[tid] = eidx[NE + e0 + tid];   // edge_index[1] = dst (x_i / agg idx)
    }
    __syncthreads();

    float4 ba = *(const float4*)(b1 + c0);
    float4 bb = *(const float4*)(b1 + c0 + 4);
    u64t acc[8][4];
#pragma unroll
    for (int r = 0; r < 8; ++r) {
        int d = sdst[row_base + r];
        int s = ssrc[row_base + r];
        float4 Pa = *(const float4*)(g_P + (size_t)d * LDIM + c0);
        float4 Pb = *(const float4*)(g_P + (size_t)d * LDIM + c0 + 4);
        float4 Qa = *(const float4*)(g_Q + (size_t)s * LDIM + c0);
        float4 Qb = *(const float4*)(g_Q + (size_t)s * LDIM + c0 + 4);
        acc[r][0] = pack2(ba.x + Pa.x + Qa.x, ba.y + Pa.y + Qa.y);
        acc[r][1] = pack2(ba.z + Pa.z + Qa.z, ba.w + Pa.w + Qa.w);
        acc[r][2] = pack2(bb.x + Pb.x + Qb.x, bb.y + Pb.y + Qb.y);
        acc[r][3] = pack2(bb.z + Pb.z + Qb.z, bb.w + Pb.w + Qb.w);
    }
    gemm_cp<KH, ASTR>(As, Ws, row_base, c0, acc);
    __syncthreads();
    cp_f4(Ws, wl + 256 * LDIM + WS_FLOATS, WS_FLOATS, tid);  // W1c rows 64..127
    __syncthreads();
    gemm_cp<KH, ASTR>(As + KH, Ws, row_base, c0, acc);

    float al = *aslope;
    __syncthreads();
    store_U(As, acc, row_base, c0, al);
    cp_f4(Ws, w2, WS_FLOATS, tid);                        // W2 rows 0..63
    __syncthreads();

    acc_initb(acc, b2, c0);
    gemm_cp<KH, ASTR>(As, Ws, row_base, c0, acc);
    __syncthreads();
    cp_f4(Ws, w2 + WS_FLOATS, WS_FLOATS, tid);            // W2 rows 64..127
    __syncthreads();
    gemm_cp<KH, ASTR>(As + KH, Ws, row_base, c0, acc);

    // scatter-add m into agg[dst] (m never materialized)
#pragma unroll
    for (int r = 0; r < 8; ++r) {
        int d = sdst[row_base + r];
        float4 lo, hi; acc_fin2(acc[r], lo, hi);
        red_add_v4(g_agg + (size_t)d * LDIM + c0, lo);
        red_add_v4(g_agg + (size_t)d * LDIM + c0 + 4, hi);
    }
}

// ============================ per-layer: node update ============================
__global__ __launch_bounds__(NT, 2)
void node_kernel(const float* __restrict__ wn1,  // ln_w1 layer base [256,128]
                 const float* __restrict__ b1, const float* __restrict__ aslope,
                 const float* __restrict__ w2, const float* __restrict__ b2) {
    extern __shared__ float sm[];
    float* Ws = sm;
    float* As = sm + WS_FLOATS;
    int tid = threadIdx.x;
    int row_base, c0; tmap(tid, row_base, c0);
    int r0 = blockIdx.x * TILE;

    fill_rows(As, g_h, r0, NN, tid);
    cp_f4(Ws, wn1, WS_FLOATS, tid);                   // rows 0..63 (h side)
    __syncthreads();

    u64t acc[8][4];
    acc_initb(acc, b1, c0);
    gemm_cp<KH, ASTR>(As, Ws, row_base, c0, acc);
    __syncthreads();
    cp_f4(Ws, wn1 + WS_FLOATS, WS_FLOATS, tid);       // rows 64..127
    __syncthreads();
    gemm_cp<KH, ASTR>(As + KH, Ws, row_base, c0, acc);

    __syncthreads();
    fill_rows(As, g_agg, r0, NN, tid);
    cp_f4(Ws, wn1 + 2 * WS_FLOATS, WS_FLOATS, tid);   // rows 128..191 (agg side)
    __syncthreads();
    gemm_cp<KH, ASTR>(As, Ws, row_base, c0, acc);
    __syncthreads();
    cp_f4(Ws, wn1 + 3 * WS_FLOATS, WS_FLOATS, tid);   // rows 192..255
    __syncthreads();
    gemm_cp<KH, ASTR>(As + KH, Ws, row_base, c0, acc);

    float al = *aslope;
    __syncthreads();
    store_U(As, acc, row_base, c0, al);
    cp_f4(Ws, w2, WS_FLOATS, tid);                    // W2 rows 0..63
    __syncthreads();

    acc_initb(acc, b2, c0);
    gemm_cp<KH, ASTR>(As, Ws, row_base, c0, acc);
    __syncthreads();
    cp_f4(Ws, w2 + WS_FLOATS, WS_FLOATS, tid);        // W2 rows 64..127
    __syncthreads();
    gemm_cp<KH, ASTR>(As + KH, Ws, row_base, c0, acc);

#pragma unroll
    for (int r = 0; r < 8; ++r) {
        int gr = r0 + row_base + r;
        if (gr < NN) {
            float4 lo, hi; acc_fin2(acc[r], lo, hi);
            float* hp = g_h + (size_t)gr * LDIM + c0;
            float4 h0 = *(float4*)(hp);
            float4 h1 = *(float4*)(hp + 4);
            h0.x += lo.x; h0.y += lo.y; h0.z += lo.z; h0.w += lo.w;
            h1.x += hi.x; h1.y += hi.y; h1.z += hi.z; h1.w += hi.w;
            *(float4*)(hp)     = h0;                       // h = h + upd
            *(float4*)(hp + 4) = h1;
        }
    }
}

// ============================ decoder ============================
__global__ __launch_bounds__(NT, 2)
void dec_kernel(const float* __restrict__ w1, const float* __restrict__ b1,
                const float* __restrict__ aslope,
                const float* __restrict__ w2, const float* __restrict__ b2,
                float* __restrict__ out) {
    extern __shared__ float sm[];
    float* Ws = sm;
    float* As = sm + WS_FLOATS;
    int tid = threadIdx.x;
    int row_base, c0; tmap(tid, row_base, c0);
    int r0 = blockIdx.x * TILE;

    fill_rows(As, g_h, r0, NN, tid);
    cp_f4(Ws, w1, WS_FLOATS, tid);
    __syncthreads();

    u64t acc[8][4];
    acc_initb(acc, b1, c0);
    gemm_cp<KH, ASTR>(As, Ws, row_base, c0, acc);
    __syncthreads();
    cp_f4(Ws, w1 + WS_FLOATS, WS_FLOATS, tid);
    __syncthreads();
    gemm_cp<KH, ASTR>(As + KH, Ws, row_base, c0, acc);

    float al = *aslope;
    __syncthreads();
    store_U(As, acc, row_base, c0, al);
    __syncthreads();

    for (int idx = tid; idx < TILE * 3; idx += NT) {
        int r = idx / 3, c = idx - r * 3;
        int gr = r0 + r;
        if (gr < NN) {
            float s = b2[c];
#pragma unroll 8
            for (int k = 0; k < LDIM; ++k)
                s = fmaf(As[r * ASTR + k], w2[k * 3 + c], s);
            out[(size_t)gr * 3 + c] = s;
        }
    }
}

// ============================ host ============================
extern "C" void kernel_launch(void* const* d_in, const int* in_sizes, int n_in,
                              void* d_out, int out_size) {
    const float* x          = (const float*)d_in[0];
    const float* edge_attr  = (const float*)d_in[1];
    const int*   edge_index = (const int*)  d_in[2];
    const float* ne_w1 = (const float*)d_in[3];
    const float* ne_b1 = (const float*)d_in[4];
    const float* ne_a  = (const float*)d_in[5];
    const float* ne_w2 = (const float*)d_in[6];
    const float* ne_b2 = (const float*)d_in[7];
    const float* ee_w1 = (const float*)d_in[8];
    const float* ee_b1 = (const float*)d_in[9];
    const float* ee_a  = (const float*)d_in[10];
    const float* ee_w2 = (const float*)d_in[11];
    const float* ee_b2 = (const float*)d_in[12];
    const float* le_w1 = (const float*)d_in[13];
    const float* le_b1 = (const float*)d_in[14];
    const float* le_a  = (const float*)d_in[15];
    const float* le_w2 = (const float*)d_in[16];
    const float* le_b2 = (const float*)d_in[17];
    const float* ln_w1 = (const float*)d_in[18];
    const float* ln_b1 = (const float*)d_in[19];
    const float* ln_a  = (const float*)d_in[20];
    const float* ln_w2 = (const float*)d_in[21];
    const float* ln_b2 = (const float*)d_in[22];
    const float* de_w1 = (const float*)d_in[23];
    const float* de_b1 = (const float*)d_in[24];
    const float* de_a  = (const float*)d_in[25];
    const float* de_w2 = (const float*)d_in[26];
    const float* de_b2 = (const float*)d_in[27];
    float* out = (float*)d_out;

    float *p_h = nullptr, *p_e = nullptr;
    cudaGetSymbolAddress((void**)&p_h, g_h);
    cudaGetSymbolAddress((void**)&p_e, g_e);

    cudaFuncSetAttribute((const void*)encoder_kernel<30,32>, cudaFuncAttributeMaxDynamicSharedMemorySize, SMEM_MAIN);
    cudaFuncSetAttribute((const void*)encoder_kernel<4,4>,   cudaFuncAttributeMaxDynamicSharedMemorySize, SMEM_MAIN);
    cudaFuncSetAttribute((const void*)pq_kernel,   cudaFuncAttributeMaxDynamicSharedMemorySize, SMEM_MAIN);
    cudaFuncSetAttribute((const void*)edge_kernel, cudaFuncAttributeMaxDynamicSharedMemorySize, SMEM_EDGE);
    cudaFuncSetAttribute((const void*)node_kernel, cudaFuncAttributeMaxDynamicSharedMemorySize, SMEM_MAIN);
    cudaFuncSetAttribute((const void*)dec_kernel,  cudaFuncAttributeMaxDynamicSharedMemorySize, SMEM_MAIN);

    const int nb_n = (NN + TILE - 1) / TILE;   // 157
    const int nb_e = NE / TILE;                // 2500

    encoder_kernel<30,32><<<nb_n, NT, SMEM_MAIN>>>(x, ne_w1, ne_b1, ne_a, ne_w2, ne_b2, p_h, NN);
    encoder_kernel<4,4>  <<<nb_e, NT, SMEM_MAIN>>>(edge_attr, ee_w1, ee_b1, ee_a, ee_w2, ee_b2, p_e, NE);

    for (int l = 0; l < NLAYERS; ++l) {
        const float* wl = le_w1 + (size_t)l * 384 * LDIM;
        pq_kernel<<<nb_n, NT, SMEM_MAIN>>>(wl);
        edge_kernel<<<nb_e, NT, SMEM_EDGE>>>(edge_index, wl,
                                             le_b1 + l * LDIM, le_a + l,
                                             le_w2 + (size_t)l * LDIM * LDIM,
                                             le_b2 + l * LDIM);
        node_kernel<<<nb_n, NT, SMEM_MAIN>>>(ln_w1 + (size_t)l * 256 * LDIM,
                                             ln_b1 + l * LDIM, ln_a + l,
                                             ln_w2 + (size_t)l * LDIM * LDIM,
                                             ln_b2 + l * LDIM);
    }
    dec_kernel<<<nb_n, NT, SMEM_MAIN>>>(de_w1, de_b1, de_a, de_w2, de_b2, out);
}

// round 10
// speedup vs baseline: 1.5672x; 1.0665x over previous
#include <cuda_runtime.h>

#define NN 20000
#define NE 320000
#define LDIM 128
#define TILE 128              // rows per CTA
#define ASTR 132              // padded A/U row stride (floats)
#define NT 256
#define KH 64                 // k-half staged in smem
#define CHI 64                // column offset of second 4-col chunk per lane
#define NLAYERS 5

// -------- scratch (static device allocations; no runtime alloc) --------
__device__ float g_h[NN * LDIM];     // node features
__device__ float g_P[NN * LDIM];     // h @ W1a  (dst-side precontraction)
__device__ float g_Q[NN * LDIM];     // h @ W1b  (src-side precontraction)
__device__ float g_agg[NN * LDIM];   // segment sum accumulator
__device__ float g_e[NE * LDIM];     // encoded edge features (constant over layers)

typedef unsigned long long u64t;

// -------- packed fp32x2 primitives --------
__device__ __forceinline__ void ffma2(u64t& d, u64t a, u64t b) {
    asm("fma.rn.f32x2 %0, %1, %2, %0;" : "+l"(d) : "l"(a), "l"(b));
}
__device__ __forceinline__ u64t pack2(float x, float y) {
    u64t v; asm("mov.b64 %0, {%1, %2};" : "=l"(v) : "f"(x), "f"(y)); return v;
}
__device__ __forceinline__ float2 unpack2(u64t v) {
    float2 f; asm("mov.b64 {%0, %1}, %2;" : "=f"(f.x), "=f"(f.y) : "l"(v)); return f;
}
__device__ __forceinline__ float prelu1(float v, float a) { return v > 0.f ? v : a * v; }

__device__ __forceinline__ void red_add_v4(float* addr, float4 v) {
    asm volatile("red.global.add.v4.f32 [%0], {%1,%2,%3,%4};"
                 :: "l"(addr), "f"(v.x), "f"(v.y), "f"(v.z), "f"(v.w)
                 : "memory");
}

// -------- smem fills --------
__device__ __forceinline__ void cp_f4(float* dst, const float* __restrict__ src,
                                      int n, int tid) {
    for (int i = tid * 4; i < n; i += NT * 4)
        *(float4*)(dst + i) = *(const float4*)(src + i);
}

// TILE x 128 row tile from [nrows,128] (clamped rows) into padded As[TILE][ASTR]
__device__ __forceinline__ void fill_rows(float* As, const float* __restrict__ src,
                                          int r0, int nrows, int tid) {
    for (int i = tid * 4; i < TILE * LDIM; i += NT * 4) {
        int r = i >> 7;
        int k = i & (LDIM - 1);
        int gr = r0 + r; if (gr >= nrows) gr = nrows - 1;
        *(float4*)(As + r * ASTR + k) = *(const float4*)(src + (size_t)gr * LDIM + k);
    }
}

// -------- core packed GEMM (column-paired accumulators, 16 rows/warp) --------
// Warp covers 16 rows (2 x 8-row halves via ly). Each thread: 8 rows x 8 cols,
// cols split into two contiguous-across-lanes chunks: [c0..c0+3] and [c0+CHI..+3].
// acc[r][0..1] -> chunk lo, acc[r][2..3] -> chunk hi (each f32x2 = 2 adjacent cols).
template<int K, int AS>
__device__ __forceinline__ void gemm_cp(const float* __restrict__ As,
                                        const float* __restrict__ Ws,
                                        int row_base, int c0, u64t acc[8][4]) {
#pragma unroll 2
    for (int k = 0; k < K; k += 4) {
        float4 av[8];
#pragma unroll
        for (int r = 0; r < 8; ++r)
            av[r] = *(const float4*)(As + (row_base + r) * AS + k);
#pragma unroll
        for (int kk = 0; kk < 4; ++kk) {
            const float* wr = Ws + (k + kk) * LDIM + c0;
            ulonglong2 w0 = *(const ulonglong2*)(wr);          // cols c0..c0+3
            ulonglong2 w1 = *(const ulonglong2*)(wr + CHI);    // cols c0+64..+67
#pragma unroll
            for (int r = 0; r < 8; ++r) {
                float a = (kk == 0) ? av[r].x : (kk == 1) ? av[r].y
                        : (kk == 2) ? av[r].z : av[r].w;
                u64t ad = pack2(a, a);
                ffma2(acc[r][0], ad, w0.x);
                ffma2(acc[r][1], ad, w0.y);
                ffma2(acc[r][2], ad, w1.x);
                ffma2(acc[r][3], ad, w1.y);
            }
        }
    }
}

__device__ __forceinline__ void acc_initb(u64t acc[8][4], const float* __restrict__ b, int c0) {
    ulonglong2 b0 = *(const ulonglong2*)(b + c0);
    ulonglong2 b1 = *(const ulonglong2*)(b + c0 + CHI);
#pragma unroll
    for (int r = 0; r < 8; ++r) {
        acc[r][0] = b0.x; acc[r][1] = b0.y; acc[r][2] = b1.x; acc[r][3] = b1.y;
    }
}
__device__ __forceinline__ void acc_init0(u64t acc[8][4]) {
#pragma unroll
    for (int r = 0; r < 8; ++r)
        acc[r][0] = acc[r][1] = acc[r][2] = acc[r][3] = 0ull;
}
// lo = cols c0..c0+3, hi = cols c0+CHI..c0+CHI+3
__device__ __forceinline__ void acc_fin2(const u64t a[4], float4& lo, float4& hi) {
    float2 f0 = unpack2(a[0]), f1 = unpack2(a[1]), f2 = unpack2(a[2]), f3 = unpack2(a[3]);
    lo = make_float4(f0.x, f0.y, f1.x, f1.y);
    hi = make_float4(f2.x, f2.y, f3.x, f3.y);
}

// prelu(acc) -> U (padded stride ASTR)
__device__ __forceinline__ void store_U(float* U, u64t acc[8][4],
                                        int row_base, int c0, float al) {
#pragma unroll
    for (int r = 0; r < 8; ++r) {
        float4 lo, hi; acc_fin2(acc[r], lo, hi);
        lo.x = prelu1(lo.x, al); lo.y = prelu1(lo.y, al);
        lo.z = prelu1(lo.z, al); lo.w = prelu1(lo.w, al);
        hi.x = prelu1(hi.x, al); hi.y = prelu1(hi.y, al);
        hi.z = prelu1(hi.z, al); hi.w = prelu1(hi.w, al);
        float* p = U + (row_base + r) * ASTR + c0;
        *(float4*)(p)       = lo;
        *(float4*)(p + CHI) = hi;
    }
}

// thread -> (row_base, c0): warp wy covers rows wy*16..+15 (ly: 8-row half),
// lx -> cols {lx*4..+3} and {64+lx*4..+3}
__device__ __forceinline__ void tmap(int tid, int& row_base, int& c0) {
    int wy = tid >> 5;
    int lane = tid & 31;
    row_base = wy * 16 + (lane >> 4) * 8;
    c0 = (lane & 15) * 4;
}

// shared layout: Ws [KH][128] (32KB), then As/U [TILE][ASTR]
#define WS_FLOATS (KH * LDIM)
#define SMEM_MAIN ((WS_FLOATS + TILE * ASTR) * 4)
#define SMEM_EDGE (SMEM_MAIN + 2 * TILE * 4)

// ============================ encoder (node / edge) ============================
template<int K1, int K1P>
__global__ __launch_bounds__(NT, 2)
void encoder_kernel(const float* __restrict__ in,
                    const float* __restrict__ w1, const float* __restrict__ b1,
                    const float* __restrict__ aslope,
                    const float* __restrict__ w2, const float* __restrict__ b2,
                    float* __restrict__ out, int nrows) {
    extern __shared__ float sm[];
    float* Ws = sm;
    float* As = sm + WS_FLOATS;
    int tid = threadIdx.x;
    int row_base, c0; tmap(tid, row_base, c0);
    int r0 = blockIdx.x * TILE;

    for (int i = tid; i < TILE * K1P; i += NT) {
        int r = i / K1P, k = i - r * K1P;
        int gr = r0 + r; if (gr >= nrows) gr = nrows - 1;
        As[i] = (k < K1) ? in[(size_t)gr * K1 + k] : 0.f;
    }
    for (int i = tid; i < K1P * LDIM; i += NT)
        Ws[i] = (i < K1 * LDIM) ? w1[i] : 0.f;
    __syncthreads();

    u64t acc[8][4];
    acc_initb(acc, b1, c0);
    gemm_cp<K1P, K1P>(As, Ws, row_base, c0, acc);

    float al = *aslope;
    __syncthreads();
    store_U(As, acc, row_base, c0, al);
    cp_f4(Ws, w2, WS_FLOATS, tid);
    __syncthreads();

    acc_initb(acc, b2, c0);
    gemm_cp<KH, ASTR>(As, Ws, row_base, c0, acc);
    __syncthreads();
    cp_f4(Ws, w2 + WS_FLOATS, WS_FLOATS, tid);
    __syncthreads();
    gemm_cp<KH, ASTR>(As + KH, Ws, row_base, c0, acc);

#pragma unroll
    for (int r = 0; r < 8; ++r) {
        int gr = r0 + row_base + r;
        if (gr < nrows) {
            float4 lo, hi; acc_fin2(acc[r], lo, hi);
            *(float4*)(out + (size_t)gr * LDIM + c0)       = lo;
            *(float4*)(out + (size_t)gr * LDIM + c0 + CHI) = hi;
        }
    }
}

// ============================ per-layer: P/Q + zero agg ============================
__global__ __launch_bounds__(NT, 2)
void pq_kernel(const float* __restrict__ wl /* le_w1 layer base [384,128] */) {
    extern __shared__ float sm[];
    float* Ws = sm;
    float* As = sm + WS_FLOATS;
    int tid = threadIdx.x;
    int row_base, c0; tmap(tid, row_base, c0);
    int r0 = blockIdx.x * TILE;

    fill_rows(As, g_h, r0, NN, tid);
    cp_f4(Ws, wl, WS_FLOATS, tid);                    // W1a rows 0..63
    __syncthreads();

    float4 z = make_float4(0.f, 0.f, 0.f, 0.f);
    u64t acc[8][4];
    acc_init0(acc);
    gemm_cp<KH, ASTR>(As, Ws, row_base, c0, acc);
    __syncthreads();
    cp_f4(Ws, wl + WS_FLOATS, WS_FLOATS, tid);        // W1a rows 64..127
    __syncthreads();
    gemm_cp<KH, ASTR>(As + KH, Ws, row_base, c0, acc);
#pragma unroll
    for (int r = 0; r < 8; ++r) {
        int gr = r0 + row_base + r;
        if (gr < NN) {
            float4 lo, hi; acc_fin2(acc[r], lo, hi);
            *(float4*)(g_P + (size_t)gr * LDIM + c0)         = lo;
            *(float4*)(g_P + (size_t)gr * LDIM + c0 + CHI)   = hi;
            *(float4*)(g_agg + (size_t)gr * LDIM + c0)       = z;
            *(float4*)(g_agg + (size_t)gr * LDIM + c0 + CHI) = z;
        }
    }
    __syncthreads();
    cp_f4(Ws, wl + 2 * WS_FLOATS, WS_FLOATS, tid);    // W1b rows 0..63
    __syncthreads();
    acc_init0(acc);
    gemm_cp<KH, ASTR>(As, Ws, row_base, c0, acc);
    __syncthreads();
    cp_f4(Ws, wl + 3 * WS_FLOATS, WS_FLOATS, tid);    // W1b rows 64..127
    __syncthreads();
    gemm_cp<KH, ASTR>(As + KH, Ws, row_base, c0, acc);
#pragma unroll
    for (int r = 0; r < 8; ++r) {
        int gr = r0 + row_base + r;
        if (gr < NN) {
            float4 lo, hi; acc_fin2(acc[r], lo, hi);
            *(float4*)(g_Q + (size_t)gr * LDIM + c0)       = lo;
            *(float4*)(g_Q + (size_t)gr * LDIM + c0 + CHI) = hi;
        }
    }
}

// ============================ per-layer: edge messages + scatter ============================
__global__ __launch_bounds__(NT, 2)
void edge_kernel(const int* __restrict__ eidx,
                 const float* __restrict__ wl,    // le_w1 layer base [384,128]
                 const float* __restrict__ b1, const float* __restrict__ aslope,
                 const float* __restrict__ w2, const float* __restrict__ b2) {
    extern __shared__ float sm[];
    float* Ws = sm;
    float* As = sm + WS_FLOATS;
    int* sdst = (int*)(As + TILE * ASTR);
    int* ssrc = sdst + TILE;
    int tid = threadIdx.x;
    int row_base, c0; tmap(tid, row_base, c0);
    size_t e0 = (size_t)blockIdx.x * TILE;

    fill_rows(As, g_e + e0 * LDIM, 0, TILE, tid);       // e tile (contiguous rows)
    cp_f4(Ws, wl + 256 * LDIM, WS_FLOATS, tid);          // W1c rows 0..63
    if (tid < TILE) {
        ssrc[tid] = eidx[e0 + tid];        // edge_index[0] = src (x_j)
        sdst[tid] = eidx[NE + e0 + tid];   // edge_index[1] = dst (x_i / agg idx)
    }
    __syncthreads();

    float4 ba = *(const float4*)(b1 + c0);
    float4 bb = *(const float4*)(b1 + c0 + CHI);
    u64t acc[8][4];
#pragma unroll
    for (int r = 0; r < 8; ++r) {
        int d = sdst[row_base + r];
        int s = ssrc[row_base + r];
        float4 Pa = *(const float4*)(g_P + (size_t)d * LDIM + c0);
        float4 Pb = *(const float4*)(g_P + (size_t)d * LDIM + c0 + CHI);
        float4 Qa = *(const float4*)(g_Q + (size_t)s * LDIM + c0);
        float4 Qb = *(const float4*)(g_Q + (size_t)s * LDIM + c0 + CHI);
        acc[r][0] = pack2(ba.x + Pa.x + Qa.x, ba.y + Pa.y + Qa.y);
        acc[r][1] = pack2(ba.z + Pa.z + Qa.z, ba.w + Pa.w + Qa.w);
        acc[r][2] = pack2(bb.x + Pb.x + Qb.x, bb.y + Pb.y + Qb.y);
        acc[r][3] = pack2(bb.z + Pb.z + Qb.z, bb.w + Pb.w + Qb.w);
    }
    gemm_cp<KH, ASTR>(As, Ws, row_base, c0, acc);
    __syncthreads();
    cp_f4(Ws, wl + 256 * LDIM + WS_FLOATS, WS_FLOATS, tid);  // W1c rows 64..127
    __syncthreads();
    gemm_cp<KH, ASTR>(As + KH, Ws, row_base, c0, acc);

    float al = *aslope;
    __syncthreads();
    store_U(As, acc, row_base, c0, al);
    cp_f4(Ws, w2, WS_FLOATS, tid);                        // W2 rows 0..63
    __syncthreads();

    acc_initb(acc, b2, c0);
    gemm_cp<KH, ASTR>(As, Ws, row_base, c0, acc);
    __syncthreads();
    cp_f4(Ws, w2 + WS_FLOATS, WS_FLOATS, tid);            // W2 rows 64..127
    __syncthreads();
    gemm_cp<KH, ASTR>(As + KH, Ws, row_base, c0, acc);

    // scatter-add m into agg[dst] (m never materialized)
#pragma unroll
    for (int r = 0; r < 8; ++r) {
        int d = sdst[row_base + r];
        float4 lo, hi; acc_fin2(acc[r], lo, hi);
        red_add_v4(g_agg + (size_t)d * LDIM + c0, lo);
        red_add_v4(g_agg + (size_t)d * LDIM + c0 + CHI, hi);
    }
}

// ============================ per-layer: node update ============================
__global__ __launch_bounds__(NT, 2)
void node_kernel(const float* __restrict__ wn1,  // ln_w1 layer base [256,128]
                 const float* __restrict__ b1, const float* __restrict__ aslope,
                 const float* __restrict__ w2, const float* __restrict__ b2) {
    extern __shared__ float sm[];
    float* Ws = sm;
    float* As = sm + WS_FLOATS;
    int tid = threadIdx.x;
    int row_base, c0; tmap(tid, row_base, c0);
    int r0 = blockIdx.x * TILE;

    fill_rows(As, g_h, r0, NN, tid);
    cp_f4(Ws, wn1, WS_FLOATS, tid);                   // rows 0..63 (h side)
    __syncthreads();

    u64t acc[8][4];
    acc_initb(acc, b1, c0);
    gemm_cp<KH, ASTR>(As, Ws, row_base, c0, acc);
    __syncthreads();
    cp_f4(Ws, wn1 + WS_FLOATS, WS_FLOATS, tid);       // rows 64..127
    __syncthreads();
    gemm_cp<KH, ASTR>(As + KH, Ws, row_base, c0, acc);

    __syncthreads();
    fill_rows(As, g_agg, r0, NN, tid);
    cp_f4(Ws, wn1 + 2 * WS_FLOATS, WS_FLOATS, tid);   // rows 128..191 (agg side)
    __syncthreads();
    gemm_cp<KH, ASTR>(As, Ws, row_base, c0, acc);
    __syncthreads();
    cp_f4(Ws, wn1 + 3 * WS_FLOATS, WS_FLOATS, tid);   // rows 192..255
    __syncthreads();
    gemm_cp<KH, ASTR>(As + KH, Ws, row_base, c0, acc);

    float al = *aslope;
    __syncthreads();
    store_U(As, acc, row_base, c0, al);
    cp_f4(Ws, w2, WS_FLOATS, tid);                    // W2 rows 0..63
    __syncthreads();

    acc_initb(acc, b2, c0);
    gemm_cp<KH, ASTR>(As, Ws, row_base, c0, acc);
    __syncthreads();
    cp_f4(Ws, w2 + WS_FLOATS, WS_FLOATS, tid);        // W2 rows 64..127
    __syncthreads();
    gemm_cp<KH, ASTR>(As + KH, Ws, row_base, c0, acc);

#pragma unroll
    for (int r = 0; r < 8; ++r) {
        int gr = r0 + row_base + r;
        if (gr < NN) {
            float4 lo, hi; acc_fin2(acc[r], lo, hi);
            float* hp = g_h + (size_t)gr * LDIM + c0;
            float4 h0 = *(float4*)(hp);
            float4 h1 = *(float4*)(hp + CHI);
            h0.x += lo.x; h0.y += lo.y; h0.z += lo.z; h0.w += lo.w;
            h1.x += hi.x; h1.y += hi.y; h1.z += hi.z; h1.w += hi.w;
            *(float4*)(hp)       = h0;                     // h = h + upd
            *(float4*)(hp + CHI) = h1;
        }
    }
}

// ============================ decoder ============================
__global__ __launch_bounds__(NT, 2)
void dec_kernel(const float* __restrict__ w1, const float* __restrict__ b1,
                const float* __restrict__ aslope,
                const float* __restrict__ w2, const float* __restrict__ b2,
                float* __restrict__ out) {
    extern __shared__ float sm[];
    float* Ws = sm;
    float* As = sm + WS_FLOATS;
    int tid = threadIdx.x;
    int row_base, c0; tmap(tid, row_base, c0);
    int r0 = blockIdx.x * TILE;

    fill_rows(As, g_h, r0, NN, tid);
    cp_f4(Ws, w1, WS_FLOATS, tid);
    __syncthreads();

    u64t acc[8][4];
    acc_initb(acc, b1, c0);
    gemm_cp<KH, ASTR>(As, Ws, row_base, c0, acc);
    __syncthreads();
    cp_f4(Ws, w1 + WS_FLOATS, WS_FLOATS, tid);
    __syncthreads();
    gemm_cp<KH, ASTR>(As + KH, Ws, row_base, c0, acc);

    float al = *aslope;
    __syncthreads();
    store_U(As, acc, row_base, c0, al);
    __syncthreads();

    for (int idx = tid; idx < TILE * 3; idx += NT) {
        int r = idx / 3, c = idx - r * 3;
        int gr = r0 + r;
        if (gr < NN) {
            float s = b2[c];
#pragma unroll 8
            for (int k = 0; k < LDIM; ++k)
                s = fmaf(As[r * ASTR + k], w2[k * 3 + c], s);
            out[(size_t)gr * 3 + c] = s;
        }
    }
}

// ============================ host ============================
extern "C" void kernel_launch(void* const* d_in, const int* in_sizes, int n_in,
                              void* d_out, int out_size) {
    const float* x          = (const float*)d_in[0];
    const float* edge_attr  = (const float*)d_in[1];
    const int*   edge_index = (const int*)  d_in[2];
    const float* ne_w1 = (const float*)d_in[3];
    const float* ne_b1 = (const float*)d_in[4];
    const float* ne_a  = (const float*)d_in[5];
    const float* ne_w2 = (const float*)d_in[6];
    const float* ne_b2 = (const float*)d_in[7];
    const float* ee_w1 = (const float*)d_in[8];
    const float* ee_b1 = (const float*)d_in[9];
    const float* ee_a  = (const float*)d_in[10];
    const float* ee_w2 = (const float*)d_in[11];
    const float* ee_b2 = (const float*)d_in[12];
    const float* le_w1 = (const float*)d_in[13];
    const float* le_b1 = (const float*)d_in[14];
    const float* le_a  = (const float*)d_in[15];
    const float* le_w2 = (const float*)d_in[16];
    const float* le_b2 = (const float*)d_in[17];
    const float* ln_w1 = (const float*)d_in[18];
    const float* ln_b1 = (const float*)d_in[19];
    const float* ln_a  = (const float*)d_in[20];
    const float* ln_w2 = (const float*)d_in[21];
    const float* ln_b2 = (const float*)d_in[22];
    const float* de_w1 = (const float*)d_in[23];
    const float* de_b1 = (const float*)d_in[24];
    const float* de_a  = (const float*)d_in[25];
    const float* de_w2 = (const float*)d_in[26];
    const float* de_b2 = (const float*)d_in[27];
    float* out = (float*)d_out;

    float *p_h = nullptr, *p_e = nullptr;
    cudaGetSymbolAddress((void**)&p_h, g_h);
    cudaGetSymbolAddress((void**)&p_e, g_e);

    cudaFuncSetAttribute((const void*)encoder_kernel<30,32>, cudaFuncAttributeMaxDynamicSharedMemorySize, SMEM_MAIN);
    cudaFuncSetAttribute((const void*)encoder_kernel<4,4>,   cudaFuncAttributeMaxDynamicSharedMemorySize, SMEM_MAIN);
    cudaFuncSetAttribute((const void*)pq_kernel,   cudaFuncAttributeMaxDynamicSharedMemorySize, SMEM_MAIN);
    cudaFuncSetAttribute((const void*)edge_kernel, cudaFuncAttributeMaxDynamicSharedMemorySize, SMEM_EDGE);
    cudaFuncSetAttribute((const void*)node_kernel, cudaFuncAttributeMaxDynamicSharedMemorySize, SMEM_MAIN);
    cudaFuncSetAttribute((const void*)dec_kernel,  cudaFuncAttributeMaxDynamicSharedMemorySize, SMEM_MAIN);

    const int nb_n = (NN + TILE - 1) / TILE;   // 157
    const int nb_e = NE / TILE;                // 2500

    encoder_kernel<30,32><<<nb_n, NT, SMEM_MAIN>>>(x, ne_w1, ne_b1, ne_a, ne_w2, ne_b2, p_h, NN);
    encoder_kernel<4,4>  <<<nb_e, NT, SMEM_MAIN>>>(edge_attr, ee_w1, ee_b1, ee_a, ee_w2, ee_b2, p_e, NE);

    for (int l = 0; l < NLAYERS; ++l) {
        const float* wl = le_w1 + (size_t)l * 384 * LDIM;
        pq_kernel<<<nb_n, NT, SMEM_MAIN>>>(wl);
        edge_kernel<<<nb_e, NT, SMEM_EDGE>>>(edge_index, wl,
                                             le_b1 + l * LDIM, le_a + l,
                                             le_w2 + (size_t)l * LDIM * LDIM,
                                             le_b2 + l * LDIM);
        node_kernel<<<nb_n, NT, SMEM_MAIN>>>(ln_w1 + (size_t)l * 256 * LDIM,
                                             ln_b1 + l * LDIM, ln_a + l,
                                             ln_w2 + (size_t)l * LDIM * LDIM,
                                             ln_b2 + l * LDIM);
    }
    dec_kernel<<<nb_n, NT, SMEM_MAIN>>>(de_w1, de_b1, de_a, de_w2, de_b2, out);
}

// round 11
// speedup vs baseline: 1.7013x; 1.0855x over previous
#include <cuda_runtime.h>
#include <stdint.h>

#define NN 20000
#define NE 320000
#define LDIM 128
#define TILE 128              // rows per CTA
#define ASTR 132              // padded A/U row stride (floats)
#define NT 256
#define KQ 32                 // k-quarter staged per cp.async group
#define CHI 64                // column offset of second 4-col chunk per lane
#define NLAYERS 5

#define WQ_FLOATS (KQ * LDIM)                       // 4096 floats = 16KB
#define SMEM_MAIN ((2 * WQ_FLOATS + TILE * ASTR) * 4)
#define SMEM_EDGE (SMEM_MAIN + 2 * TILE * 4)

// -------- scratch (static device allocations; no runtime alloc) --------
__device__ float g_h[NN * LDIM];
__device__ float g_P[NN * LDIM];
__device__ float g_Q[NN * LDIM];
__device__ float g_agg[NN * LDIM];
__device__ float g_e[NE * LDIM];

typedef unsigned long long u64t;

// -------- packed fp32x2 primitives --------
__device__ __forceinline__ void ffma2(u64t& d, u64t a, u64t b) {
    asm("fma.rn.f32x2 %0, %1, %2, %0;" : "+l"(d) : "l"(a), "l"(b));
}
__device__ __forceinline__ u64t pack2(float x, float y) {
    u64t v; asm("mov.b64 %0, {%1, %2};" : "=l"(v) : "f"(x), "f"(y)); return v;
}
__device__ __forceinline__ float2 unpack2(u64t v) {
    float2 f; asm("mov.b64 {%0, %1}, %2;" : "=f"(f.x), "=f"(f.y) : "l"(v)); return f;
}
__device__ __forceinline__ float prelu1(float v, float a) { return v > 0.f ? v : a * v; }

__device__ __forceinline__ void red_add_v4(float* addr, float4 v) {
    asm volatile("red.global.add.v4.f32 [%0], {%1,%2,%3,%4};"
                 :: "l"(addr), "f"(v.x), "f"(v.y), "f"(v.z), "f"(v.w)
                 : "memory");
}

// -------- cp.async staging --------
__device__ __forceinline__ uint32_t smem_u32(const void* p) {
    uint32_t a;
    asm("{ .reg .u64 t; cvta.to.shared.u64 t, %1; cvt.u32.u64 %0, t; }" : "=r"(a) : "l"(p));
    return a;
}
__device__ __forceinline__ void cpa16(uint32_t d, const float* __restrict__ s) {
    asm volatile("cp.async.cg.shared.global [%0], [%1], 16;" :: "r"(d), "l"(s));
}
// stage one 16KB W quarter (4096 floats) as ONE commit group (all 256 threads)
__device__ __forceinline__ void stage_w(float* buf, const float* __restrict__ w, int tid) {
    uint32_t d = smem_u32(buf + tid * 4);
    const float* s = w + tid * 4;
#pragma unroll
    for (int i = 0; i < WQ_FLOATS / (NT * 4); ++i)
        cpa16(d + i * NT * 16, s + i * NT * 4);
    asm volatile("cp.async.commit_group;" ::: "memory");
}
#define CPA_WAIT_ALL() asm volatile("cp.async.wait_group 0;" ::: "memory")

// -------- smem fills --------
__device__ __forceinline__ void fill_rows(float* As, const float* __restrict__ src,
                                          int r0, int nrows, int tid) {
    for (int i = tid * 4; i < TILE * LDIM; i += NT * 4) {
        int r = i >> 7;
        int k = i & (LDIM - 1);
        int gr = r0 + r; if (gr >= nrows) gr = nrows - 1;
        *(float4*)(As + r * ASTR + k) = *(const float4*)(src + (size_t)gr * LDIM + k);
    }
}

// -------- core packed GEMM (column-paired accumulators, 16 rows/warp) --------
template<int K, int AS>
__device__ __forceinline__ void gemm_cp(const float* __restrict__ As,
                                        const float* __restrict__ Ws,
                                        int row_base, int c0, u64t acc[8][4]) {
#pragma unroll 2
    for (int k = 0; k < K; k += 4) {
        float4 av[8];
#pragma unroll
        for (int r = 0; r < 8; ++r)
            av[r] = *(const float4*)(As + (row_base + r) * AS + k);
#pragma unroll
        for (int kk = 0; kk < 4; ++kk) {
            const float* wr = Ws + (k + kk) * LDIM + c0;
            ulonglong2 w0 = *(const ulonglong2*)(wr);          // cols c0..c0+3
            ulonglong2 w1 = *(const ulonglong2*)(wr + CHI);    // cols c0+64..+67
#pragma unroll
            for (int r = 0; r < 8; ++r) {
                float a = (kk == 0) ? av[r].x : (kk == 1) ? av[r].y
                        : (kk == 2) ? av[r].z : av[r].w;
                u64t ad = pack2(a, a);
                ffma2(acc[r][0], ad, w0.x);
                ffma2(acc[r][1], ad, w0.y);
                ffma2(acc[r][2], ad, w1.x);
                ffma2(acc[r][3], ad, w1.y);
            }
        }
    }
}

__device__ __forceinline__ void acc_initb(u64t acc[8][4], const float* __restrict__ b, int c0) {
    ulonglong2 b0 = *(const ulonglong2*)(b + c0);
    ulonglong2 b1 = *(const ulonglong2*)(b + c0 + CHI);
#pragma unroll
    for (int r = 0; r < 8; ++r) {
        acc[r][0] = b0.x; acc[r][1] = b0.y; acc[r][2] = b1.x; acc[r][3] = b1.y;
    }
}
__device__ __forceinline__ void acc_init0(u64t acc[8][4]) {
#pragma unroll
    for (int r = 0; r < 8; ++r)
        acc[r][0] = acc[r][1] = acc[r][2] = acc[r][3] = 0ull;
}
__device__ __forceinline__ void acc_fin2(const u64t a[4], float4& lo, float4& hi) {
    float2 f0 = unpack2(a[0]), f1 = unpack2(a[1]), f2 = unpack2(a[2]), f3 = unpack2(a[3]);
    lo = make_float4(f0.x, f0.y, f1.x, f1.y);
    hi = make_float4(f2.x, f2.y, f3.x, f3.y);
}
__device__ __forceinline__ void store_U(float* U, u64t acc[8][4],
                                        int row_base, int c0, float al) {
#pragma unroll
    for (int r = 0; r < 8; ++r) {
        float4 lo, hi; acc_fin2(acc[r], lo, hi);
        lo.x = prelu1(lo.x, al); lo.y = prelu1(lo.y, al);
        lo.z = prelu1(lo.z, al); lo.w = prelu1(lo.w, al);
        hi.x = prelu1(hi.x, al); hi.y = prelu1(hi.y, al);
        hi.z = prelu1(hi.z, al); hi.w = prelu1(hi.w, al);
        float* p = U + (row_base + r) * ASTR + c0;
        *(float4*)(p)       = lo;
        *(float4*)(p + CHI) = hi;
    }
}
__device__ __forceinline__ void tmap(int tid, int& row_base, int& c0) {
    int wy = tid >> 5;
    int lane = tid & 31;
    row_base = wy * 16 + (lane >> 4) * 8;
    c0 = (lane & 15) * 4;
}

// Run 4 streamed quarters of one 128-K GEMM. q0 must already be staged into Wb0
// parity slot (global quarter index base even -> starts at Wb0). nxt = source of the
// quarter AFTER this GEMM (or nullptr).
#define GEMM_STREAM4(Wb0, Wb1, As, wsrc, nxt, row_base, c0, acc)                        \
    do {                                                                                \
        _Pragma("unroll")                                                               \
        for (int q = 0; q < 4; ++q) {                                                   \
            CPA_WAIT_ALL(); __syncthreads();                                            \
            const float* _n = (q < 3) ? ((wsrc) + (q + 1) * WQ_FLOATS) : (nxt);         \
            if (_n) stage_w((q & 1) ? (Wb0) : (Wb1), _n, tid);                          \
            gemm_cp<KQ, ASTR>((As) + q * KQ, (q & 1) ? (Wb1) : (Wb0), row_base, c0, acc);\
        }                                                                               \
    } while (0)

// ============================ encoder (node / edge) ============================
template<int K1, int K1P>
__global__ __launch_bounds__(NT, 2)
void encoder_kernel(const float* __restrict__ in,
                    const float* __restrict__ w1, const float* __restrict__ b1,
                    const float* __restrict__ aslope,
                    const float* __restrict__ w2, const float* __restrict__ b2,
                    float* __restrict__ out, int nrows) {
    extern __shared__ float sm[];
    float* Wb0 = sm;
    float* Wb1 = sm + WQ_FLOATS;
    float* As = sm + 2 * WQ_FLOATS;
    int tid = threadIdx.x;
    int row_base, c0; tmap(tid, row_base, c0);
    int r0 = blockIdx.x * TILE;

    // A tile [TILE][K1P] zero-padded; W1 into Wb0 (fits: K1P<=32)
    for (int i = tid; i < TILE * K1P; i += NT) {
        int r = i / K1P, k = i - r * K1P;
        int gr = r0 + r; if (gr >= nrows) gr = nrows - 1;
        As[i] = (k < K1) ? in[(size_t)gr * K1 + k] : 0.f;
    }
    for (int i = tid; i < K1P * LDIM; i += NT)
        Wb0[i] = (i < K1 * LDIM) ? w1[i] : 0.f;
    __syncthreads();

    stage_w(Wb1, w2, tid);                 // prefetch W2 q0 during GEMM1 (q0 -> Wb1!)
    float al = *aslope;

    u64t acc[8][4];
    acc_initb(acc, b1, c0);
    gemm_cp<K1P, K1P>(As, Wb0, row_base, c0, acc);

    __syncthreads();                       // all reads of As/Wb0 done
    store_U(As, acc, row_base, c0, al);
    acc_initb(acc, b2, c0);

    // W2 quarters with flipped parity: q0->Wb1, q1->Wb0, ...
#pragma unroll
    for (int q = 0; q < 4; ++q) {
        CPA_WAIT_ALL(); __syncthreads();
        if (q < 3) stage_w((q & 1) ? Wb1 : Wb0, w2 + (q + 1) * WQ_FLOATS, tid);
        gemm_cp<KQ, ASTR>(As + q * KQ, (q & 1) ? Wb0 : Wb1, row_base, c0, acc);
    }

#pragma unroll
    for (int r = 0; r < 8; ++r) {
        int gr = r0 + row_base + r;
        if (gr < nrows) {
            float4 lo, hi; acc_fin2(acc[r], lo, hi);
            *(float4*)(out + (size_t)gr * LDIM + c0)       = lo;
            *(float4*)(out + (size_t)gr * LDIM + c0 + CHI) = hi;
        }
    }
}

// ============================ per-layer: P/Q + zero agg ============================
__global__ __launch_bounds__(NT, 2)
void pq_kernel(const float* __restrict__ wl) {
    extern __shared__ float sm[];
    float* Wb0 = sm;
    float* Wb1 = sm + WQ_FLOATS;
    float* As = sm + 2 * WQ_FLOATS;
    int tid = threadIdx.x;
    int row_base, c0; tmap(tid, row_base, c0);
    int r0 = blockIdx.x * TILE;

    stage_w(Wb0, wl, tid);                           // W1a q0
    fill_rows(As, g_h, r0, NN, tid);
    __syncthreads();

    const float* w1b = wl + 4 * WQ_FLOATS;
    float4 z = make_float4(0.f, 0.f, 0.f, 0.f);
    u64t acc[8][4];
    acc_init0(acc);
    GEMM_STREAM4(Wb0, Wb1, As, wl, w1b, row_base, c0, acc);   // W1a, prefetch W1b q0
#pragma unroll
    for (int r = 0; r < 8; ++r) {
        int gr = r0 + row_base + r;
        if (gr < NN) {
            float4 lo, hi; acc_fin2(acc[r], lo, hi);
            *(float4*)(g_P + (size_t)gr * LDIM + c0)         = lo;
            *(float4*)(g_P + (size_t)gr * LDIM + c0 + CHI)   = hi;
            *(float4*)(g_agg + (size_t)gr * LDIM + c0)       = z;
            *(float4*)(g_agg + (size_t)gr * LDIM + c0 + CHI) = z;
        }
    }
    acc_init0(acc);
    GEMM_STREAM4(Wb0, Wb1, As, w1b, (const float*)0, row_base, c0, acc);  // W1b
#pragma unroll
    for (int r = 0; r < 8; ++r) {
        int gr = r0 + row_base + r;
        if (gr < NN) {
            float4 lo, hi; acc_fin2(acc[r], lo, hi);
            *(float4*)(g_Q + (size_t)gr * LDIM + c0)       = lo;
            *(float4*)(g_Q + (size_t)gr * LDIM + c0 + CHI) = hi;
        }
    }
}

// ============================ per-layer: edge messages + scatter ============================
__global__ __launch_bounds__(NT, 2)
void edge_kernel(const int* __restrict__ eidx,
                 const float* __restrict__ wl,
                 const float* __restrict__ b1, const float* __restrict__ aslope,
                 const float* __restrict__ w2, const float* __restrict__ b2) {
    extern __shared__ float sm[];
    float* Wb0 = sm;
    float* Wb1 = sm + WQ_FLOATS;
    float* As = sm + 2 * WQ_FLOATS;
    int* sdst = (int*)(As + TILE * ASTR);
    int* ssrc = sdst + TILE;
    int tid = threadIdx.x;
    int row_base, c0; tmap(tid, row_base, c0);
    size_t e0 = (size_t)blockIdx.x * TILE;

    const float* w1c = wl + 256 * LDIM;
    stage_w(Wb0, w1c, tid);                          // W1c q0
    fill_rows(As, g_e + e0 * LDIM, 0, TILE, tid);
    if (tid < TILE) {
        ssrc[tid] = eidx[e0 + tid];
        sdst[tid] = eidx[NE + e0 + tid];
    }
    __syncthreads();

    float al = *aslope;
    float4 ba = *(const float4*)(b1 + c0);
    float4 bb = *(const float4*)(b1 + c0 + CHI);
    u64t acc[8][4];
#pragma unroll
    for (int r = 0; r < 8; ++r) {
        int d = sdst[row_base + r];
        int s = ssrc[row_base + r];
        float4 Pa = *(const float4*)(g_P + (size_t)d * LDIM + c0);
        float4 Pb = *(const float4*)(g_P + (size_t)d * LDIM + c0 + CHI);
        float4 Qa = *(const float4*)(g_Q + (size_t)s * LDIM + c0);
        float4 Qb = *(const float4*)(g_Q + (size_t)s * LDIM + c0 + CHI);
        acc[r][0] = pack2(ba.x + Pa.x + Qa.x, ba.y + Pa.y + Qa.y);
        acc[r][1] = pack2(ba.z + Pa.z + Qa.z, ba.w + Pa.w + Qa.w);
        acc[r][2] = pack2(bb.x + Pb.x + Qb.x, bb.y + Pb.y + Qb.y);
        acc[r][3] = pack2(bb.z + Pb.z + Qb.z, bb.w + Pb.w + Qb.w);
    }
    GEMM_STREAM4(Wb0, Wb1, As, w1c, w2, row_base, c0, acc);   // W1c, prefetch W2 q0

    __syncthreads();                       // all reads of As done
    store_U(As, acc, row_base, c0, al);
    acc_initb(acc, b2, c0);
    GEMM_STREAM4(Wb0, Wb1, As, w2, (const float*)0, row_base, c0, acc);  // W2

#pragma unroll
    for (int r = 0; r < 8; ++r) {
        int d = sdst[row_base + r];
        float4 lo, hi; acc_fin2(acc[r], lo, hi);
        red_add_v4(g_agg + (size_t)d * LDIM + c0, lo);
        red_add_v4(g_agg + (size_t)d * LDIM + c0 + CHI, hi);
    }
}

// ============================ per-layer: node update ============================
__global__ __launch_bounds__(NT, 2)
void node_kernel(const float* __restrict__ wn1,
                 const float* __restrict__ b1, const float* __restrict__ aslope,
                 const float* __restrict__ w2, const float* __restrict__ b2) {
    extern __shared__ float sm[];
    float* Wb0 = sm;
    float* Wb1 = sm + WQ_FLOATS;
    float* As = sm + 2 * WQ_FLOATS;
    int tid = threadIdx.x;
    int row_base, c0; tmap(tid, row_base, c0);
    int r0 = blockIdx.x * TILE;

    const float* wagg = wn1 + 4 * WQ_FLOATS;         // agg-side rows 128..255
    stage_w(Wb0, wn1, tid);                          // h-side q0
    fill_rows(As, g_h, r0, NN, tid);
    __syncthreads();

    float al = *aslope;
    u64t acc[8][4];
    acc_initb(acc, b1, c0);
    GEMM_STREAM4(Wb0, Wb1, As, wn1, wagg, row_base, c0, acc);   // h side, prefetch agg q0

    __syncthreads();                      // As free
    fill_rows(As, g_agg, r0, NN, tid);
    GEMM_STREAM4(Wb0, Wb1, As, wagg, w2, row_base, c0, acc);    // agg side, prefetch W2 q0

    __syncthreads();
    store_U(As, acc, row_base, c0, al);
    acc_initb(acc, b2, c0);
    GEMM_STREAM4(Wb0, Wb1, As, w2, (const float*)0, row_base, c0, acc);  // W2

#pragma unroll
    for (int r = 0; r < 8; ++r) {
        int gr = r0 + row_base + r;
        if (gr < NN) {
            float4 lo, hi; acc_fin2(acc[r], lo, hi);
            float* hp = g_h + (size_t)gr * LDIM + c0;
            float4 h0 = *(float4*)(hp);
            float4 h1 = *(float4*)(hp + CHI);
            h0.x += lo.x; h0.y += lo.y; h0.z += lo.z; h0.w += lo.w;
            h1.x += hi.x; h1.y += hi.y; h1.z += hi.z; h1.w += hi.w;
            *(float4*)(hp)       = h0;
            *(float4*)(hp + CHI) = h1;
        }
    }
}

// ============================ decoder ============================
__global__ __launch_bounds__(NT, 2)
void dec_kernel(const float* __restrict__ w1, const float* __restrict__ b1,
                const float* __restrict__ aslope,
                const float* __restrict__ w2, const float* __restrict__ b2,
                float* __restrict__ out) {
    extern __shared__ float sm[];
    float* Wb0 = sm;
    float* Wb1 = sm + WQ_FLOATS;
    float* As = sm + 2 * WQ_FLOATS;
    int tid = threadIdx.x;
    int row_base, c0; tmap(tid, row_base, c0);
    int r0 = blockIdx.x * TILE;

    stage_w(Wb0, w1, tid);
    fill_rows(As, g_h, r0, NN, tid);
    __syncthreads();

    float al = *aslope;
    u64t acc[8][4];
    acc_initb(acc, b1, c0);
    GEMM_STREAM4(Wb0, Wb1, As, w1, (const float*)0, row_base, c0, acc);

    __syncthreads();
    store_U(As, acc, row_base, c0, al);
    __syncthreads();

    for (int idx = tid; idx < TILE * 3; idx += NT) {
        int r = idx / 3, c = idx - r * 3;
        int gr = r0 + r;
        if (gr < NN) {
            float s = b2[c];
#pragma unroll 8
            for (int k = 0; k < LDIM; ++k)
                s = fmaf(As[r * ASTR + k], w2[k * 3 + c], s);
            out[(size_t)gr * 3 + c] = s;
        }
    }
}

// ============================ host ============================
extern "C" void kernel_launch(void* const* d_in, const int* in_sizes, int n_in,
                              void* d_out, int out_size) {
    const float* x          = (const float*)d_in[0];
    const float* edge_attr  = (const float*)d_in[1];
    const int*   edge_index = (const int*)  d_in[2];
    const float* ne_w1 = (const float*)d_in[3];
    const float* ne_b1 = (const float*)d_in[4];
    const float* ne_a  = (const float*)d_in[5];
    const float* ne_w2 = (const float*)d_in[6];
    const float* ne_b2 = (const float*)d_in[7];
    const float* ee_w1 = (const float*)d_in[8];
    const float* ee_b1 = (const float*)d_in[9];
    const float* ee_a  = (const float*)d_in[10];
    const float* ee_w2 = (const float*)d_in[11];
    const float* ee_b2 = (const float*)d_in[12];
    const float* le_w1 = (const float*)d_in[13];
    const float* le_b1 = (const float*)d_in[14];
    const float* le_a  = (const float*)d_in[15];
    const float* le_w2 = (const float*)d_in[16];
    const float* le_b2 = (const float*)d_in[17];
    const float* ln_w1 = (const float*)d_in[18];
    const float* ln_b1 = (const float*)d_in[19];
    const float* ln_a  = (const float*)d_in[20];
    const float* ln_w2 = (const float*)d_in[21];
    const float* ln_b2 = (const float*)d_in[22];
    const float* de_w1 = (const float*)d_in[23];
    const float* de_b1 = (const float*)d_in[24];
    const float* de_a  = (const float*)d_in[25];
    const float* de_w2 = (const float*)d_in[26];
    const float* de_b2 = (const float*)d_in[27];
    float* out = (float*)d_out;

    float *p_h = nullptr, *p_e = nullptr;
    cudaGetSymbolAddress((void**)&p_h, g_h);
    cudaGetSymbolAddress((void**)&p_e, g_e);

    cudaFuncSetAttribute((const void*)encoder_kernel<30,32>, cudaFuncAttributeMaxDynamicSharedMemorySize, SMEM_MAIN);
    cudaFuncSetAttribute((const void*)encoder_kernel<4,4>,   cudaFuncAttributeMaxDynamicSharedMemorySize, SMEM_MAIN);
    cudaFuncSetAttribute((const void*)pq_kernel,   cudaFuncAttributeMaxDynamicSharedMemorySize, SMEM_MAIN);
    cudaFuncSetAttribute((const void*)edge_kernel, cudaFuncAttributeMaxDynamicSharedMemorySize, SMEM_EDGE);
    cudaFuncSetAttribute((const void*)node_kernel, cudaFuncAttributeMaxDynamicSharedMemorySize, SMEM_MAIN);
    cudaFuncSetAttribute((const void*)dec_kernel,  cudaFuncAttributeMaxDynamicSharedMemorySize, SMEM_MAIN);

    const int nb_n = (NN + TILE - 1) / TILE;   // 157
    const int nb_e = NE / TILE;                // 2500

    encoder_kernel<30,32><<<nb_n, NT, SMEM_MAIN>>>(x, ne_w1, ne_b1, ne_a, ne_w2, ne_b2, p_h, NN);
    encoder_kernel<4,4>  <<<nb_e, NT, SMEM_MAIN>>>(edge_attr, ee_w1, ee_b1, ee_a, ee_w2, ee_b2, p_e, NE);

    for (int l = 0; l < NLAYERS; ++l) {
        const float* wl = le_w1 + (size_t)l * 384 * LDIM;
        pq_kernel<<<nb_n, NT, SMEM_MAIN>>>(wl);
        edge_kernel<<<nb_e, NT, SMEM_EDGE>>>(edge_index, wl,
                                             le_b1 + l * LDIM, le_a + l,
                                             le_w2 + (size_t)l * LDIM * LDIM,
                                             le_b2 + l * LDIM);
        node_kernel<<<nb_n, NT, SMEM_MAIN>>>(ln_w1 + (size_t)l * 256 * LDIM,
                                             ln_b1 + l * LDIM, ln_a + l,
                                             ln_w2 + (size_t)l * LDIM * LDIM,
                                             ln_b2 + l * LDIM);
    }
    dec_kernel<<<nb_n, NT, SMEM_MAIN>>>(de_w1, de_b1, de_a, de_w2, de_b2, out);
}

// round 12
// speedup vs baseline: 1.7203x; 1.0112x over previous
#include <cuda_runtime.h>
#include <stdint.h>

#define NN 20000
#define NE 320000
#define LDIM 128
#define TILE 128              // rows per CTA
#define ASTR 132              // padded A/U row stride (floats)
#define NT 256
#define KQ 32                 // k-quarter staged per cp.async group
#define CHI 64                // column offset of second 4-col chunk per lane
#define NLAYERS 5

#define WQ_FLOATS (KQ * LDIM)                       // 4096 floats = 16KB
#define SMEM_MAIN ((2 * WQ_FLOATS + TILE * ASTR) * 4)
#define SMEM_EDGE (SMEM_MAIN + 2 * TILE * 4)

// -------- scratch (static device allocations; no runtime alloc) --------
__device__ float g_h[NN * LDIM];
__device__ float g_P[NN * LDIM];
__device__ float g_Q[NN * LDIM];
__device__ float g_agg[NN * LDIM];
__device__ float g_e[NE * LDIM];

typedef unsigned long long u64t;

// -------- packed fp32x2 primitives --------
__device__ __forceinline__ void ffma2(u64t& d, u64t a, u64t b) {
    asm("fma.rn.f32x2 %0, %1, %2, %0;" : "+l"(d) : "l"(a), "l"(b));
}
__device__ __forceinline__ u64t pack2(float x, float y) {
    u64t v; asm("mov.b64 %0, {%1, %2};" : "=l"(v) : "f"(x), "f"(y)); return v;
}
__device__ __forceinline__ float2 unpack2(u64t v) {
    float2 f; asm("mov.b64 {%0, %1}, %2;" : "=f"(f.x), "=f"(f.y) : "l"(v)); return f;
}
__device__ __forceinline__ float prelu1(float v, float a) { return v > 0.f ? v : a * v; }

__device__ __forceinline__ void red_add_v4(float* addr, float4 v) {
    asm volatile("red.global.add.v4.f32 [%0], {%1,%2,%3,%4};"
                 :: "l"(addr), "f"(v.x), "f"(v.y), "f"(v.z), "f"(v.w)
                 : "memory");
}

// -------- cp.async staging --------
__device__ __forceinline__ uint32_t smem_u32(const void* p) {
    uint32_t a;
    asm("{ .reg .u64 t; cvta.to.shared.u64 t, %1; cvt.u32.u64 %0, t; }" : "=r"(a) : "l"(p));
    return a;
}
__device__ __forceinline__ void cpa16(uint32_t d, const float* __restrict__ s) {
    asm volatile("cp.async.cg.shared.global [%0], [%1], 16;" :: "r"(d), "l"(s));
}
// stage one 16KB W quarter (4096 floats) as ONE commit group (all 256 threads)
__device__ __forceinline__ void stage_w(float* buf, const float* __restrict__ w, int tid) {
    uint32_t d = smem_u32(buf + tid * 4);
    const float* s = w + tid * 4;
#pragma unroll
    for (int i = 0; i < WQ_FLOATS / (NT * 4); ++i)
        cpa16(d + i * NT * 16, s + i * NT * 4);
    asm volatile("cp.async.commit_group;" ::: "memory");
}
#define CPA_WAIT_ALL() asm volatile("cp.async.wait_group 0;" ::: "memory")

// -------- smem fills --------
__device__ __forceinline__ void fill_rows(float* As, const float* __restrict__ src,
                                          int r0, int nrows, int tid) {
    for (int i = tid * 4; i < TILE * LDIM; i += NT * 4) {
        int r = i >> 7;
        int k = i & (LDIM - 1);
        int gr = r0 + r; if (gr >= nrows) gr = nrows - 1;
        *(float4*)(As + r * ASTR + k) = *(const float4*)(src + (size_t)gr * LDIM + k);
    }
}

// -------- core packed GEMM (column-paired accumulators, 16 rows/warp) --------
template<int K, int AS>
__device__ __forceinline__ void gemm_cp(const float* __restrict__ As,
                                        const float* __restrict__ Ws,
                                        int row_base, int c0, u64t acc[8][4]) {
#pragma unroll 2
    for (int k = 0; k < K; k += 4) {
        float4 av[8];
#pragma unroll
        for (int r = 0; r < 8; ++r)
            av[r] = *(const float4*)(As + (row_base + r) * AS + k);
#pragma unroll
        for (int kk = 0; kk < 4; ++kk) {
            const float* wr = Ws + (k + kk) * LDIM + c0;
            ulonglong2 w0 = *(const ulonglong2*)(wr);          // cols c0..c0+3
            ulonglong2 w1 = *(const ulonglong2*)(wr + CHI);    // cols c0+64..+67
#pragma unroll
            for (int r = 0; r < 8; ++r) {
                float a = (kk == 0) ? av[r].x : (kk == 1) ? av[r].y
                        : (kk == 2) ? av[r].z : av[r].w;
                u64t ad = pack2(a, a);
                ffma2(acc[r][0], ad, w0.x);
                ffma2(acc[r][1], ad, w0.y);
                ffma2(acc[r][2], ad, w1.x);
                ffma2(acc[r][3], ad, w1.y);
            }
        }
    }
}

__device__ __forceinline__ void acc_initb(u64t acc[8][4], const float* __restrict__ b, int c0) {
    ulonglong2 b0 = *(const ulonglong2*)(b + c0);
    ulonglong2 b1 = *(const ulonglong2*)(b + c0 + CHI);
#pragma unroll
    for (int r = 0; r < 8; ++r) {
        acc[r][0] = b0.x; acc[r][1] = b0.y; acc[r][2] = b1.x; acc[r][3] = b1.y;
    }
}
__device__ __forceinline__ void acc_init0(u64t acc[8][4]) {
#pragma unroll
    for (int r = 0; r < 8; ++r)
        acc[r][0] = acc[r][1] = acc[r][2] = acc[r][3] = 0ull;
}
__device__ __forceinline__ void acc_fin2(const u64t a[4], float4& lo, float4& hi) {
    float2 f0 = unpack2(a[0]), f1 = unpack2(a[1]), f2 = unpack2(a[2]), f3 = unpack2(a[3]);
    lo = make_float4(f0.x, f0.y, f1.x, f1.y);
    hi = make_float4(f2.x, f2.y, f3.x, f3.y);
}
__device__ __forceinline__ void store_U(float* U, u64t acc[8][4],
                                        int row_base, int c0, float al) {
#pragma unroll
    for (int r = 0; r < 8; ++r) {
        float4 lo, hi; acc_fin2(acc[r], lo, hi);
        lo.x = prelu1(lo.x, al); lo.y = prelu1(lo.y, al);
        lo.z = prelu1(lo.z, al); lo.w = prelu1(lo.w, al);
        hi.x = prelu1(hi.x, al); hi.y = prelu1(hi.y, al);
        hi.z = prelu1(hi.z, al); hi.w = prelu1(hi.w, al);
        float* p = U + (row_base + r) * ASTR + c0;
        *(float4*)(p)       = lo;
        *(float4*)(p + CHI) = hi;
    }
}
__device__ __forceinline__ void tmap(int tid, int& row_base, int& c0) {
    int wy = tid >> 5;
    int lane = tid & 31;
    row_base = wy * 16 + (lane >> 4) * 8;
    c0 = (lane & 15) * 4;
}

// Run 4 streamed quarters of one 128-K GEMM. q0 must already be staged into WbA.
// nxt = source of the quarter AFTER this GEMM (staged into WbA again), or null.
#define GEMM_STREAM4(WbA, WbB, As, wsrc, nxt, row_base, c0, acc)                         \
    do {                                                                                 \
        _Pragma("unroll")                                                                \
        for (int q = 0; q < 4; ++q) {                                                    \
            CPA_WAIT_ALL(); __syncthreads();                                             \
            const float* _n = (q < 3) ? ((wsrc) + (q + 1) * WQ_FLOATS) : (nxt);          \
            if (_n) stage_w((q & 1) ? (WbA) : (WbB), _n, tid);                           \
            gemm_cp<KQ, ASTR>((As) + q * KQ, (q & 1) ? (WbB) : (WbA), row_base, c0, acc);\
        }                                                                                \
    } while (0)

// write P/agg-zero epilogue
__device__ __forceinline__ void store_P_agg(u64t acc[8][4], int r0, int row_base, int c0) {
    float4 z = make_float4(0.f, 0.f, 0.f, 0.f);
#pragma unroll
    for (int r = 0; r < 8; ++r) {
        int gr = r0 + row_base + r;
        if (gr < NN) {
            float4 lo, hi; acc_fin2(acc[r], lo, hi);
            *(float4*)(g_P + (size_t)gr * LDIM + c0)         = lo;
            *(float4*)(g_P + (size_t)gr * LDIM + c0 + CHI)   = hi;
            *(float4*)(g_agg + (size_t)gr * LDIM + c0)       = z;
            *(float4*)(g_agg + (size_t)gr * LDIM + c0 + CHI) = z;
        }
    }
}
__device__ __forceinline__ void store_Qv(u64t acc[8][4], int r0, int row_base, int c0) {
#pragma unroll
    for (int r = 0; r < 8; ++r) {
        int gr = r0 + row_base + r;
        if (gr < NN) {
            float4 lo, hi; acc_fin2(acc[r], lo, hi);
            *(float4*)(g_Q + (size_t)gr * LDIM + c0)       = lo;
            *(float4*)(g_Q + (size_t)gr * LDIM + c0 + CHI) = hi;
        }
    }
}

// ============================ encoder (node fused with layer-0 P/Q; edge plain) ====
template<int K1, int K1P>
__global__ __launch_bounds__(NT, 2)
void encoder_kernel(const float* __restrict__ in,
                    const float* __restrict__ w1, const float* __restrict__ b1,
                    const float* __restrict__ aslope,
                    const float* __restrict__ w2, const float* __restrict__ b2,
                    float* __restrict__ out, int nrows,
                    const float* __restrict__ wl /* le_w1 layer0 base or null */) {
    extern __shared__ float sm[];
    float* Wb0 = sm;
    float* Wb1 = sm + WQ_FLOATS;
    float* As = sm + 2 * WQ_FLOATS;
    int tid = threadIdx.x;
    int row_base, c0; tmap(tid, row_base, c0);
    int r0 = blockIdx.x * TILE;

    // A tile [TILE][K1P] zero-padded; W1 into Wb0 (fits: K1P<=32)
    for (int i = tid; i < TILE * K1P; i += NT) {
        int r = i / K1P, k = i - r * K1P;
        int gr = r0 + r; if (gr >= nrows) gr = nrows - 1;
        As[i] = (k < K1) ? in[(size_t)gr * K1 + k] : 0.f;
    }
    for (int i = tid; i < K1P * LDIM; i += NT)
        Wb0[i] = (i < K1 * LDIM) ? w1[i] : 0.f;
    __syncthreads();

    stage_w(Wb1, w2, tid);                 // prefetch W2 q0 during GEMM1 (q0 -> Wb1)
    float al = *aslope;

    u64t acc[8][4];
    acc_initb(acc, b1, c0);
    gemm_cp<K1P, K1P>(As, Wb0, row_base, c0, acc);

    __syncthreads();                       // all reads of As/Wb0 done
    store_U(As, acc, row_base, c0, al);
    acc_initb(acc, b2, c0);

    GEMM_STREAM4(Wb1, Wb0, As, w2, wl, row_base, c0, acc);   // h; prefetch W1a q0

    // h -> out (and As for P/Q when fused)
    __syncthreads();                       // gemm reads of As done
#pragma unroll
    for (int r = 0; r < 8; ++r) {
        int gr = r0 + row_base + r;
        float4 lo, hi; acc_fin2(acc[r], lo, hi);
        if (gr < nrows) {
            *(float4*)(out + (size_t)gr * LDIM + c0)       = lo;
            *(float4*)(out + (size_t)gr * LDIM + c0 + CHI) = hi;
        }
        if (wl) {
            float* p = As + (row_base + r) * ASTR + c0;
            *(float4*)(p)       = lo;
            *(float4*)(p + CHI) = hi;
        }
    }
    if (!wl) return;
    __syncthreads();

    const float* w1b = wl + 4 * WQ_FLOATS;
    acc_init0(acc);
    GEMM_STREAM4(Wb1, Wb0, As, wl, w1b, row_base, c0, acc);   // P
    store_P_agg(acc, r0, row_base, c0);
    acc_init0(acc);
    GEMM_STREAM4(Wb1, Wb0, As, w1b, (const float*)0, row_base, c0, acc);  // Q
    store_Qv(acc, r0, row_base, c0);
}

// ============================ per-layer: edge messages + scatter ============================
__global__ __launch_bounds__(NT, 2)
void edge_kernel(const int* __restrict__ eidx,
                 const float* __restrict__ wl,
                 const float* __restrict__ b1, const float* __restrict__ aslope,
                 const float* __restrict__ w2, const float* __restrict__ b2) {
    extern __shared__ float sm[];
    float* Wb0 = sm;
    float* Wb1 = sm + WQ_FLOATS;
    float* As = sm + 2 * WQ_FLOATS;
    int* sdst = (int*)(As + TILE * ASTR);
    int* ssrc = sdst + TILE;
    int tid = threadIdx.x;
    int row_base, c0; tmap(tid, row_base, c0);
    size_t e0 = (size_t)blockIdx.x * TILE;

    const float* w1c = wl + 256 * LDIM;
    stage_w(Wb0, w1c, tid);                          // W1c q0
    fill_rows(As, g_e + e0 * LDIM, 0, TILE, tid);
    if (tid < TILE) {
        ssrc[tid] = eidx[e0 + tid];
        sdst[tid] = eidx[NE + e0 + tid];
    }
    __syncthreads();

    float al = *aslope;
    float4 ba = *(const float4*)(b1 + c0);
    float4 bb = *(const float4*)(b1 + c0 + CHI);
    u64t acc[8][4];
#pragma unroll
    for (int r = 0; r < 8; ++r) {
        int d = sdst[row_base + r];
        int s = ssrc[row_base + r];
        float4 Pa = *(const float4*)(g_P + (size_t)d * LDIM + c0);
        float4 Pb = *(const float4*)(g_P + (size_t)d * LDIM + c0 + CHI);
        float4 Qa = *(const float4*)(g_Q + (size_t)s * LDIM + c0);
        float4 Qb = *(const float4*)(g_Q + (size_t)s * LDIM + c0 + CHI);
        acc[r][0] = pack2(ba.x + Pa.x + Qa.x, ba.y + Pa.y + Qa.y);
        acc[r][1] = pack2(ba.z + Pa.z + Qa.z, ba.w + Pa.w + Qa.w);
        acc[r][2] = pack2(bb.x + Pb.x + Qb.x, bb.y + Pb.y + Qb.y);
        acc[r][3] = pack2(bb.z + Pb.z + Qb.z, bb.w + Pb.w + Qb.w);
    }
    GEMM_STREAM4(Wb0, Wb1, As, w1c, w2, row_base, c0, acc);   // W1c, prefetch W2 q0

    __syncthreads();
    store_U(As, acc, row_base, c0, al);
    acc_initb(acc, b2, c0);
    GEMM_STREAM4(Wb0, Wb1, As, w2, (const float*)0, row_base, c0, acc);  // W2

#pragma unroll
    for (int r = 0; r < 8; ++r) {
        int d = sdst[row_base + r];
        float4 lo, hi; acc_fin2(acc[r], lo, hi);
        red_add_v4(g_agg + (size_t)d * LDIM + c0, lo);
        red_add_v4(g_agg + (size_t)d * LDIM + c0 + CHI, hi);
    }
}

// ============================ per-layer: node update (fused with next-layer P/Q) ====
__global__ __launch_bounds__(NT, 2)
void node_kernel(const float* __restrict__ wn1,
                 const float* __restrict__ b1, const float* __restrict__ aslope,
                 const float* __restrict__ w2, const float* __restrict__ b2,
                 const float* __restrict__ wl_next /* le_w1 next layer or null */) {
    extern __shared__ float sm[];
    float* Wb0 = sm;
    float* Wb1 = sm + WQ_FLOATS;
    float* As = sm + 2 * WQ_FLOATS;
    int tid = threadIdx.x;
    int row_base, c0; tmap(tid, row_base, c0);
    int r0 = blockIdx.x * TILE;

    const float* wagg = wn1 + 4 * WQ_FLOATS;
    stage_w(Wb0, wn1, tid);
    fill_rows(As, g_h, r0, NN, tid);
    __syncthreads();

    float al = *aslope;
    u64t acc[8][4];
    acc_initb(acc, b1, c0);
    GEMM_STREAM4(Wb0, Wb1, As, wn1, wagg, row_base, c0, acc);   // h side

    __syncthreads();
    fill_rows(As, g_agg, r0, NN, tid);
    GEMM_STREAM4(Wb0, Wb1, As, wagg, w2, row_base, c0, acc);    // agg side

    __syncthreads();
    store_U(As, acc, row_base, c0, al);
    acc_initb(acc, b2, c0);
    GEMM_STREAM4(Wb0, Wb1, As, w2, wl_next, row_base, c0, acc); // W2; prefetch W1a q0

    // h update epilogue: h_new -> g_h (and As for fused P/Q)
    __syncthreads();
#pragma unroll
    for (int r = 0; r < 8; ++r) {
        int gr = r0 + row_base + r;
        if (gr < NN) {
            float4 lo, hi; acc_fin2(acc[r], lo, hi);
            float* hp = g_h + (size_t)gr * LDIM + c0;
            float4 h0 = *(float4*)(hp);
            float4 h1 = *(float4*)(hp + CHI);
            h0.x += lo.x; h0.y += lo.y; h0.z += lo.z; h0.w += lo.w;
            h1.x += hi.x; h1.y += hi.y; h1.z += hi.z; h1.w += hi.w;
            *(float4*)(hp)       = h0;
            *(float4*)(hp + CHI) = h1;
            if (wl_next) {
                float* p = As + (row_base + r) * ASTR + c0;
                *(float4*)(p)       = h0;
                *(float4*)(p + CHI) = h1;
            }
        }
    }
    if (!wl_next) return;
    __syncthreads();

    const float* w1b = wl_next + 4 * WQ_FLOATS;
    acc_init0(acc);
    GEMM_STREAM4(Wb0, Wb1, As, wl_next, w1b, row_base, c0, acc);   // P
    store_P_agg(acc, r0, row_base, c0);
    acc_init0(acc);
    GEMM_STREAM4(Wb0, Wb1, As, w1b, (const float*)0, row_base, c0, acc);  // Q
    store_Qv(acc, r0, row_base, c0);
}

// ============================ decoder ============================
__global__ __launch_bounds__(NT, 2)
void dec_kernel(const float* __restrict__ w1, const float* __restrict__ b1,
                const float* __restrict__ aslope,
                const float* __restrict__ w2, const float* __restrict__ b2,
                float* __restrict__ out) {
    extern __shared__ float sm[];
    float* Wb0 = sm;
    float* Wb1 = sm + WQ_FLOATS;
    float* As = sm + 2 * WQ_FLOATS;
    int tid = threadIdx.x;
    int row_base, c0; tmap(tid, row_base, c0);
    int r0 = blockIdx.x * TILE;

    stage_w(Wb0, w1, tid);
    fill_rows(As, g_h, r0, NN, tid);
    __syncthreads();

    float al = *aslope;
    u64t acc[8][4];
    acc_initb(acc, b1, c0);
    GEMM_STREAM4(Wb0, Wb1, As, w1, (const float*)0, row_base, c0, acc);

    __syncthreads();
    store_U(As, acc, row_base, c0, al);
    __syncthreads();

    for (int idx = tid; idx < TILE * 3; idx += NT) {
        int r = idx / 3, c = idx - r * 3;
        int gr = r0 + r;
        if (gr < NN) {
            float s = b2[c];
#pragma unroll 8
            for (int k = 0; k < LDIM; ++k)
                s = fmaf(As[r * ASTR + k], w2[k * 3 + c], s);
            out[(size_t)gr * 3 + c] = s;
        }
    }
}

// ============================ host ============================
extern "C" void kernel_launch(void* const* d_in, const int* in_sizes, int n_in,
                              void* d_out, int out_size) {
    const float* x          = (const float*)d_in[0];
    const float* edge_attr  = (const float*)d_in[1];
    const int*   edge_index = (const int*)  d_in[2];
    const float* ne_w1 = (const float*)d_in[3];
    const float* ne_b1 = (const float*)d_in[4];
    const float* ne_a  = (const float*)d_in[5];
    const float* ne_w2 = (const float*)d_in[6];
    const float* ne_b2 = (const float*)d_in[7];
    const float* ee_w1 = (const float*)d_in[8];
    const float* ee_b1 = (const float*)d_in[9];
    const float* ee_a  = (const float*)d_in[10];
    const float* ee_w2 = (const float*)d_in[11];
    const float* ee_b2 = (const float*)d_in[12];
    const float* le_w1 = (const float*)d_in[13];
    const float* le_b1 = (const float*)d_in[14];
    const float* le_a  = (const float*)d_in[15];
    const float* le_w2 = (const float*)d_in[16];
    const float* le_b2 = (const float*)d_in[17];
    const float* ln_w1 = (const float*)d_in[18];
    const float* ln_b1 = (const float*)d_in[19];
    const float* ln_a  = (const float*)d_in[20];
    const float* ln_w2 = (const float*)d_in[21];
    const float* ln_b2 = (const float*)d_in[22];
    const float* de_w1 = (const float*)d_in[23];
    const float* de_b1 = (const float*)d_in[24];
    const float* de_a  = (const float*)d_in[25];
    const float* de_w2 = (const float*)d_in[26];
    const float* de_b2 = (const float*)d_in[27];
    float* out = (float*)d_out;

    float *p_h = nullptr, *p_e = nullptr;
    cudaGetSymbolAddress((void**)&p_h, g_h);
    cudaGetSymbolAddress((void**)&p_e, g_e);

    cudaFuncSetAttribute((const void*)encoder_kernel<30,32>, cudaFuncAttributeMaxDynamicSharedMemorySize, SMEM_MAIN);
    cudaFuncSetAttribute((const void*)encoder_kernel<4,4>,   cudaFuncAttributeMaxDynamicSharedMemorySize, SMEM_MAIN);
    cudaFuncSetAttribute((const void*)edge_kernel, cudaFuncAttributeMaxDynamicSharedMemorySize, SMEM_EDGE);
    cudaFuncSetAttribute((const void*)node_kernel, cudaFuncAttributeMaxDynamicSharedMemorySize, SMEM_MAIN);
    cudaFuncSetAttribute((const void*)dec_kernel,  cudaFuncAttributeMaxDynamicSharedMemorySize, SMEM_MAIN);

    const int nb_n = (NN + TILE - 1) / TILE;   // 157
    const int nb_e = NE / TILE;                // 2500

    // node encoder fused with layer-0 P/Q (+agg zero)
    encoder_kernel<30,32><<<nb_n, NT, SMEM_MAIN>>>(x, ne_w1, ne_b1, ne_a, ne_w2, ne_b2,
                                                   p_h, NN, le_w1);
    encoder_kernel<4,4>  <<<nb_e, NT, SMEM_MAIN>>>(edge_attr, ee_w1, ee_b1, ee_a, ee_w2, ee_b2,
                                                   p_e, NE, (const float*)0);

    for (int l = 0; l < NLAYERS; ++l) {
        const float* wl = le_w1 + (size_t)l * 384 * LDIM;
        edge_kernel<<<nb_e, NT, SMEM_EDGE>>>(edge_index, wl,
                                             le_b1 + l * LDIM, le_a + l,
                                             le_w2 + (size_t)l * LDIM * LDIM,
                                             le_b2 + l * LDIM);
        const float* wl_next = (l + 1 < NLAYERS) ? (le_w1 + (size_t)(l + 1) * 384 * LDIM)
                                                 : (const float*)0;
        node_kernel<<<nb_n, NT, SMEM_MAIN>>>(ln_w1 + (size_t)l * 256 * LDIM,
                                             ln_b1 + l * LDIM, ln_a + l,
                                             ln_w2 + (size_t)l * LDIM * LDIM,
                                             ln_b2 + l * LDIM,
                                             wl_next);
    }
    dec_kernel<<<nb_n, NT, SMEM_MAIN>>>(de_w1, de_b1, de_a, de_w2, de_b2, out);
}

// round 13
// speedup vs baseline: 1.8282x; 1.0627x over previous
#include <cuda_runtime.h>
#include <stdint.h>

#define NN 20000
#define NE 320000
#define LDIM 128
#define TILE 128              // rows per CTA (edge kernel)
#define TILEN 64              // rows per CTA (node-side kernels)
#define ASTR 132              // padded A/U row stride (floats)
#define NT 256                // threads (edge)
#define NTN 128               // threads (node-side)
#define KQ 32                 // k-quarter staged per cp.async group
#define CHI 64                // column offset of second 4-col chunk per lane
#define NLAYERS 5

#define WQ_FLOATS (KQ * LDIM)                       // 4096 floats = 16KB
#define SMEM_EDGEK ((2 * WQ_FLOATS + TILE * ASTR) * 4 + 2 * TILE * 4)
#define SMEM_NODE  ((2 * WQ_FLOATS + TILEN * ASTR) * 4)

// -------- scratch (static device allocations; no runtime alloc) --------
__device__ float g_h[NN * LDIM];
__device__ float g_P[NN * LDIM];
__device__ float g_Q[NN * LDIM];
__device__ float g_agg[NN * LDIM];
__device__ float g_e[NE * LDIM];

typedef unsigned long long u64t;

// -------- packed fp32x2 primitives --------
__device__ __forceinline__ void ffma2(u64t& d, u64t a, u64t b) {
    asm("fma.rn.f32x2 %0, %1, %2, %0;" : "+l"(d) : "l"(a), "l"(b));
}
__device__ __forceinline__ u64t pack2(float x, float y) {
    u64t v; asm("mov.b64 %0, {%1, %2};" : "=l"(v) : "f"(x), "f"(y)); return v;
}
__device__ __forceinline__ float2 unpack2(u64t v) {
    float2 f; asm("mov.b64 {%0, %1}, %2;" : "=f"(f.x), "=f"(f.y) : "l"(v)); return f;
}
__device__ __forceinline__ float prelu1(float v, float a) { return v > 0.f ? v : a * v; }

__device__ __forceinline__ void red_add_v4(float* addr, float4 v) {
    asm volatile("red.global.add.v4.f32 [%0], {%1,%2,%3,%4};"
                 :: "l"(addr), "f"(v.x), "f"(v.y), "f"(v.z), "f"(v.w)
                 : "memory");
}

// -------- cp.async staging --------
__device__ __forceinline__ uint32_t smem_u32(const void* p) {
    uint32_t a;
    asm("{ .reg .u64 t; cvta.to.shared.u64 t, %1; cvt.u32.u64 %0, t; }" : "=r"(a) : "l"(p));
    return a;
}
__device__ __forceinline__ void cpa16(uint32_t d, const float* __restrict__ s) {
    asm volatile("cp.async.cg.shared.global [%0], [%1], 16;" :: "r"(d), "l"(s));
}
// stage one 16KB W quarter as ONE commit group (all NTT threads)
template<int NTT>
__device__ __forceinline__ void stage_w(float* buf, const float* __restrict__ w, int tid) {
    uint32_t d = smem_u32(buf + tid * 4);
    const float* s = w + tid * 4;
#pragma unroll
    for (int i = 0; i < WQ_FLOATS / (NTT * 4); ++i)
        cpa16(d + i * NTT * 16, s + i * NTT * 4);
    asm volatile("cp.async.commit_group;" ::: "memory");
}
#define CPA_WAIT_ALL() asm volatile("cp.async.wait_group 0;" ::: "memory")

// -------- smem fills --------
template<int NTT, int TILER>
__device__ __forceinline__ void fill_rows(float* As, const float* __restrict__ src,
                                          int r0, int nrows, int tid) {
    for (int i = tid * 4; i < TILER * LDIM; i += NTT * 4) {
        int r = i >> 7;
        int k = i & (LDIM - 1);
        int gr = r0 + r; if (gr >= nrows) gr = nrows - 1;
        *(float4*)(As + r * ASTR + k) = *(const float4*)(src + (size_t)gr * LDIM + k);
    }
}

// -------- core packed GEMM (column-paired accumulators, 16 rows/warp) --------
template<int K, int AS>
__device__ __forceinline__ void gemm_cp(const float* __restrict__ As,
                                        const float* __restrict__ Ws,
                                        int row_base, int c0, u64t acc[8][4]) {
#pragma unroll 2
    for (int k = 0; k < K; k += 4) {
        float4 av[8];
#pragma unroll
        for (int r = 0; r < 8; ++r)
            av[r] = *(const float4*)(As + (row_base + r) * AS + k);
#pragma unroll
        for (int kk = 0; kk < 4; ++kk) {
            const float* wr = Ws + (k + kk) * LDIM + c0;
            ulonglong2 w0 = *(const ulonglong2*)(wr);          // cols c0..c0+3
            ulonglong2 w1 = *(const ulonglong2*)(wr + CHI);    // cols c0+64..+67
#pragma unroll
            for (int r = 0; r < 8; ++r) {
                float a = (kk == 0) ? av[r].x : (kk == 1) ? av[r].y
                        : (kk == 2) ? av[r].z : av[r].w;
                u64t ad = pack2(a, a);
                ffma2(acc[r][0], ad, w0.x);
                ffma2(acc[r][1], ad, w0.y);
                ffma2(acc[r][2], ad, w1.x);
                ffma2(acc[r][3], ad, w1.y);
            }
        }
    }
}

__device__ __forceinline__ void acc_initb(u64t acc[8][4], const float* __restrict__ b, int c0) {
    ulonglong2 b0 = *(const ulonglong2*)(b + c0);
    ulonglong2 b1 = *(const ulonglong2*)(b + c0 + CHI);
#pragma unroll
    for (int r = 0; r < 8; ++r) {
        acc[r][0] = b0.x; acc[r][1] = b0.y; acc[r][2] = b1.x; acc[r][3] = b1.y;
    }
}
__device__ __forceinline__ void acc_init0(u64t acc[8][4]) {
#pragma unroll
    for (int r = 0; r < 8; ++r)
        acc[r][0] = acc[r][1] = acc[r][2] = acc[r][3] = 0ull;
}
__device__ __forceinline__ void acc_fin2(const u64t a[4], float4& lo, float4& hi) {
    float2 f0 = unpack2(a[0]), f1 = unpack2(a[1]), f2 = unpack2(a[2]), f3 = unpack2(a[3]);
    lo = make_float4(f0.x, f0.y, f1.x, f1.y);
    hi = make_float4(f2.x, f2.y, f3.x, f3.y);
}
__device__ __forceinline__ void store_U(float* U, u64t acc[8][4],
                                        int row_base, int c0, float al) {
#pragma unroll
    for (int r = 0; r < 8; ++r) {
        float4 lo, hi; acc_fin2(acc[r], lo, hi);
        lo.x = prelu1(lo.x, al); lo.y = prelu1(lo.y, al);
        lo.z = prelu1(lo.z, al); lo.w = prelu1(lo.w, al);
        hi.x = prelu1(hi.x, al); hi.y = prelu1(hi.y, al);
        hi.z = prelu1(hi.z, al); hi.w = prelu1(hi.w, al);
        float* p = U + (row_base + r) * ASTR + c0;
        *(float4*)(p)       = lo;
        *(float4*)(p + CHI) = hi;
    }
}
__device__ __forceinline__ void tmap(int tid, int& row_base, int& c0) {
    int wy = tid >> 5;
    int lane = tid & 31;
    row_base = wy * 16 + (lane >> 4) * 8;
    c0 = (lane & 15) * 4;
}

// Run 4 streamed quarters of one 128-K GEMM. q0 must already be staged into WbA.
// nxt = source of the quarter AFTER this GEMM (staged into WbA again), or null.
#define GEMM_STREAM4(NTT, WbA, WbB, As, wsrc, nxt, row_base, c0, acc)                    \
    do {                                                                                 \
        _Pragma("unroll")                                                                \
        for (int q = 0; q < 4; ++q) {                                                    \
            CPA_WAIT_ALL(); __syncthreads();                                             \
            const float* _n = (q < 3) ? ((wsrc) + (q + 1) * WQ_FLOATS) : (nxt);          \
            if (_n) stage_w<NTT>((q & 1) ? (WbA) : (WbB), _n, tid);                      \
            gemm_cp<KQ, ASTR>((As) + q * KQ, (q & 1) ? (WbB) : (WbA), row_base, c0, acc);\
        }                                                                                \
    } while (0)

// write P/agg-zero epilogue
__device__ __forceinline__ void store_P_agg(u64t acc[8][4], int r0, int row_base, int c0) {
    float4 z = make_float4(0.f, 0.f, 0.f, 0.f);
#pragma unroll
    for (int r = 0; r < 8; ++r) {
        int gr = r0 + row_base + r;
        if (gr < NN) {
            float4 lo, hi; acc_fin2(acc[r], lo, hi);
            *(float4*)(g_P + (size_t)gr * LDIM + c0)         = lo;
            *(float4*)(g_P + (size_t)gr * LDIM + c0 + CHI)   = hi;
            *(float4*)(g_agg + (size_t)gr * LDIM + c0)       = z;
            *(float4*)(g_agg + (size_t)gr * LDIM + c0 + CHI) = z;
        }
    }
}
__device__ __forceinline__ void store_Qv(u64t acc[8][4], int r0, int row_base, int c0) {
#pragma unroll
    for (int r = 0; r < 8; ++r) {
        int gr = r0 + row_base + r;
        if (gr < NN) {
            float4 lo, hi; acc_fin2(acc[r], lo, hi);
            *(float4*)(g_Q + (size_t)gr * LDIM + c0)       = lo;
            *(float4*)(g_Q + (size_t)gr * LDIM + c0 + CHI) = hi;
        }
    }
}

// ============================ encoder (node fused with layer-0 P/Q; edge plain) ====
// Node-side config: NTN threads, TILEN rows, 3 CTAs/SM.
template<int K1, int K1P>
__global__ __launch_bounds__(NTN, 3)
void encoder_kernel(const float* __restrict__ in,
                    const float* __restrict__ w1, const float* __restrict__ b1,
                    const float* __restrict__ aslope,
                    const float* __restrict__ w2, const float* __restrict__ b2,
                    float* __restrict__ out, int nrows,
                    const float* __restrict__ wl /* le_w1 layer0 base or null */) {
    extern __shared__ float sm[];
    float* Wb0 = sm;
    float* Wb1 = sm + WQ_FLOATS;
    float* As = sm + 2 * WQ_FLOATS;
    int tid = threadIdx.x;
    int row_base, c0; tmap(tid, row_base, c0);
    int r0 = blockIdx.x * TILEN;

    // A tile [TILEN][K1P] zero-padded; W1 into Wb0 (fits: K1P<=32)
    for (int i = tid; i < TILEN * K1P; i += NTN) {
        int r = i / K1P, k = i - r * K1P;
        int gr = r0 + r; if (gr >= nrows) gr = nrows - 1;
        As[i] = (k < K1) ? in[(size_t)gr * K1 + k] : 0.f;
    }
    for (int i = tid; i < K1P * LDIM; i += NTN)
        Wb0[i] = (i < K1 * LDIM) ? w1[i] : 0.f;
    __syncthreads();

    stage_w<NTN>(Wb1, w2, tid);            // prefetch W2 q0 during GEMM1 (q0 -> Wb1)
    float al = *aslope;

    u64t acc[8][4];
    acc_initb(acc, b1, c0);
    gemm_cp<K1P, K1P>(As, Wb0, row_base, c0, acc);

    __syncthreads();                       // all reads of As/Wb0 done
    store_U(As, acc, row_base, c0, al);
    acc_initb(acc, b2, c0);

    GEMM_STREAM4(NTN, Wb1, Wb0, As, w2, wl, row_base, c0, acc);  // h; prefetch W1a q0

    __syncthreads();                       // gemm reads of As done
#pragma unroll
    for (int r = 0; r < 8; ++r) {
        int gr = r0 + row_base + r;
        float4 lo, hi; acc_fin2(acc[r], lo, hi);
        if (gr < nrows) {
            *(float4*)(out + (size_t)gr * LDIM + c0)       = lo;
            *(float4*)(out + (size_t)gr * LDIM + c0 + CHI) = hi;
        }
        if (wl) {
            float* p = As + (row_base + r) * ASTR + c0;
            *(float4*)(p)       = lo;
            *(float4*)(p + CHI) = hi;
        }
    }
    if (!wl) return;
    __syncthreads();

    const float* w1b = wl + 4 * WQ_FLOATS;
    acc_init0(acc);
    GEMM_STREAM4(NTN, Wb1, Wb0, As, wl, w1b, row_base, c0, acc);   // P
    store_P_agg(acc, r0, row_base, c0);
    acc_init0(acc);
    GEMM_STREAM4(NTN, Wb1, Wb0, As, w1b, (const float*)0, row_base, c0, acc);  // Q
    store_Qv(acc, r0, row_base, c0);
}

// ============================ per-layer: edge messages + scatter ============================
__global__ __launch_bounds__(NT, 2)
void edge_kernel(const int* __restrict__ eidx,
                 const float* __restrict__ wl,
                 const float* __restrict__ b1, const float* __restrict__ aslope,
                 const float* __restrict__ w2, const float* __restrict__ b2) {
    extern __shared__ float sm[];
    float* Wb0 = sm;
    float* Wb1 = sm + WQ_FLOATS;
    float* As = sm + 2 * WQ_FLOATS;
    int* sdst = (int*)(As + TILE * ASTR);
    int* ssrc = sdst + TILE;
    int tid = threadIdx.x;
    int row_base, c0; tmap(tid, row_base, c0);
    size_t e0 = (size_t)blockIdx.x * TILE;

    const float* w1c = wl + 256 * LDIM;
    stage_w<NT>(Wb0, w1c, tid);                      // W1c q0
    fill_rows<NT, TILE>(As, g_e + e0 * LDIM, 0, TILE, tid);
    if (tid < TILE) {
        ssrc[tid] = eidx[e0 + tid];
        sdst[tid] = eidx[NE + e0 + tid];
    }
    __syncthreads();

    float al = *aslope;
    float4 ba = *(const float4*)(b1 + c0);
    float4 bb = *(const float4*)(b1 + c0 + CHI);
    u64t acc[8][4];
#pragma unroll
    for (int r = 0; r < 8; ++r) {
        int d = sdst[row_base + r];
        int s = ssrc[row_base + r];
        float4 Pa = *(const float4*)(g_P + (size_t)d * LDIM + c0);
        float4 Pb = *(const float4*)(g_P + (size_t)d * LDIM + c0 + CHI);
        float4 Qa = *(const float4*)(g_Q + (size_t)s * LDIM + c0);
        float4 Qb = *(const float4*)(g_Q + (size_t)s * LDIM + c0 + CHI);
        acc[r][0] = pack2(ba.x + Pa.x + Qa.x, ba.y + Pa.y + Qa.y);
        acc[r][1] = pack2(ba.z + Pa.z + Qa.z, ba.w + Pa.w + Qa.w);
        acc[r][2] = pack2(bb.x + Pb.x + Qb.x, bb.y + Pb.y + Qb.y);
        acc[r][3] = pack2(bb.z + Pb.z + Qb.z, bb.w + Pb.w + Qb.w);
    }
    GEMM_STREAM4(NT, Wb0, Wb1, As, w1c, w2, row_base, c0, acc);   // W1c, prefetch W2 q0

    __syncthreads();
    store_U(As, acc, row_base, c0, al);
    acc_initb(acc, b2, c0);
    GEMM_STREAM4(NT, Wb0, Wb1, As, w2, (const float*)0, row_base, c0, acc);  // W2

#pragma unroll
    for (int r = 0; r < 8; ++r) {
        int d = sdst[row_base + r];
        float4 lo, hi; acc_fin2(acc[r], lo, hi);
        red_add_v4(g_agg + (size_t)d * LDIM + c0, lo);
        red_add_v4(g_agg + (size_t)d * LDIM + c0 + CHI, hi);
    }
}

// ============================ per-layer: node update (fused with next-layer P/Q) ====
__global__ __launch_bounds__(NTN, 3)
void node_kernel(const float* __restrict__ wn1,
                 const float* __restrict__ b1, const float* __restrict__ aslope,
                 const float* __restrict__ w2, const float* __restrict__ b2,
                 const float* __restrict__ wl_next /* le_w1 next layer or null */) {
    extern __shared__ float sm[];
    float* Wb0 = sm;
    float* Wb1 = sm + WQ_FLOATS;
    float* As = sm + 2 * WQ_FLOATS;
    int tid = threadIdx.x;
    int row_base, c0; tmap(tid, row_base, c0);
    int r0 = blockIdx.x * TILEN;

    const float* wagg = wn1 + 4 * WQ_FLOATS;
    stage_w<NTN>(Wb0, wn1, tid);
    fill_rows<NTN, TILEN>(As, g_h, r0, NN, tid);
    __syncthreads();

    float al = *aslope;
    u64t acc[8][4];
    acc_initb(acc, b1, c0);
    GEMM_STREAM4(NTN, Wb0, Wb1, As, wn1, wagg, row_base, c0, acc);   // h side

    __syncthreads();
    fill_rows<NTN, TILEN>(As, g_agg, r0, NN, tid);
    GEMM_STREAM4(NTN, Wb0, Wb1, As, wagg, w2, row_base, c0, acc);    // agg side

    __syncthreads();
    store_U(As, acc, row_base, c0, al);
    acc_initb(acc, b2, c0);
    GEMM_STREAM4(NTN, Wb0, Wb1, As, w2, wl_next, row_base, c0, acc); // W2; prefetch W1a

    __syncthreads();
#pragma unroll
    for (int r = 0; r < 8; ++r) {
        int gr = r0 + row_base + r;
        if (gr < NN) {
            float4 lo, hi; acc_fin2(acc[r], lo, hi);
            float* hp = g_h + (size_t)gr * LDIM + c0;
            float4 h0 = *(float4*)(hp);
            float4 h1 = *(float4*)(hp + CHI);
            h0.x += lo.x; h0.y += lo.y; h0.z += lo.z; h0.w += lo.w;
            h1.x += hi.x; h1.y += hi.y; h1.z += hi.z; h1.w += hi.w;
            *(float4*)(hp)       = h0;
            *(float4*)(hp + CHI) = h1;
            if (wl_next) {
                float* p = As + (row_base + r) * ASTR + c0;
                *(float4*)(p)       = h0;
                *(float4*)(p + CHI) = h1;
            }
        }
    }
    if (!wl_next) return;
    __syncthreads();

    const float* w1b = wl_next + 4 * WQ_FLOATS;
    acc_init0(acc);
    GEMM_STREAM4(NTN, Wb0, Wb1, As, wl_next, w1b, row_base, c0, acc);   // P
    store_P_agg(acc, r0, row_base, c0);
    acc_init0(acc);
    GEMM_STREAM4(NTN, Wb0, Wb1, As, w1b, (const float*)0, row_base, c0, acc);  // Q
    store_Qv(acc, r0, row_base, c0);
}

// ============================ decoder ============================
__global__ __launch_bounds__(NTN, 3)
void dec_kernel(const float* __restrict__ w1, const float* __restrict__ b1,
                const float* __restrict__ aslope,
                const float* __restrict__ w2, const float* __restrict__ b2,
                float* __restrict__ out) {
    extern __shared__ float sm[];
    float* Wb0 = sm;
    float* Wb1 = sm + WQ_FLOATS;
    float* As = sm + 2 * WQ_FLOATS;
    int tid = threadIdx.x;
    int row_base, c0; tmap(tid, row_base, c0);
    int r0 = blockIdx.x * TILEN;

    stage_w<NTN>(Wb0, w1, tid);
    fill_rows<NTN, TILEN>(As, g_h, r0, NN, tid);
    __syncthreads();

    float al = *aslope;
    u64t acc[8][4];
    acc_initb(acc, b1, c0);
    GEMM_STREAM4(NTN, Wb0, Wb1, As, w1, (const float*)0, row_base, c0, acc);

    __syncthreads();
    store_U(As, acc, row_base, c0, al);
    __syncthreads();

    for (int idx = tid; idx < TILEN * 3; idx += NTN) {
        int r = idx / 3, c = idx - r * 3;
        int gr = r0 + r;
        if (gr < NN) {
            float s = b2[c];
#pragma unroll 8
            for (int k = 0; k < LDIM; ++k)
                s = fmaf(As[r * ASTR + k], w2[k * 3 + c], s);
            out[(size_t)gr * 3 + c] = s;
        }
    }
}

// ============================ host ============================
extern "C" void kernel_launch(void* const* d_in, const int* in_sizes, int n_in,
                              void* d_out, int out_size) {
    const float* x          = (const float*)d_in[0];
    const float* edge_attr  = (const float*)d_in[1];
    const int*   edge_index = (const int*)  d_in[2];
    const float* ne_w1 = (const float*)d_in[3];
    const float* ne_b1 = (const float*)d_in[4];
    const float* ne_a  = (const float*)d_in[5];
    const float* ne_w2 = (const float*)d_in[6];
    const float* ne_b2 = (const float*)d_in[7];
    const float* ee_w1 = (const float*)d_in[8];
    const float* ee_b1 = (const float*)d_in[9];
    const float* ee_a  = (const float*)d_in[10];
    const float* ee_w2 = (const float*)d_in[11];
    const float* ee_b2 = (const float*)d_in[12];
    const float* le_w1 = (const float*)d_in[13];
    const float* le_b1 = (const float*)d_in[14];
    const float* le_a  = (const float*)d_in[15];
    const float* le_w2 = (const float*)d_in[16];
    const float* le_b2 = (const float*)d_in[17];
    const float* ln_w1 = (const float*)d_in[18];
    const float* ln_b1 = (const float*)d_in[19];
    const float* ln_a  = (const float*)d_in[20];
    const float* ln_w2 = (const float*)d_in[21];
    const float* ln_b2 = (const float*)d_in[22];
    const float* de_w1 = (const float*)d_in[23];
    const float* de_b1 = (const float*)d_in[24];
    const float* de_a  = (const float*)d_in[25];
    const float* de_w2 = (const float*)d_in[26];
    const float* de_b2 = (const float*)d_in[27];
    float* out = (float*)d_out;

    float *p_h = nullptr, *p_e = nullptr;
    cudaGetSymbolAddress((void**)&p_h, g_h);
    cudaGetSymbolAddress((void**)&p_e, g_e);

    cudaFuncSetAttribute((const void*)encoder_kernel<30,32>, cudaFuncAttributeMaxDynamicSharedMemorySize, SMEM_NODE);
    cudaFuncSetAttribute((const void*)encoder_kernel<4,4>,   cudaFuncAttributeMaxDynamicSharedMemorySize, SMEM_NODE);
    cudaFuncSetAttribute((const void*)edge_kernel, cudaFuncAttributeMaxDynamicSharedMemorySize, SMEM_EDGEK);
    cudaFuncSetAttribute((const void*)node_kernel, cudaFuncAttributeMaxDynamicSharedMemorySize, SMEM_NODE);
    cudaFuncSetAttribute((const void*)dec_kernel,  cudaFuncAttributeMaxDynamicSharedMemorySize, SMEM_NODE);

    const int nb_n = (NN + TILEN - 1) / TILEN;   // 313
    const int nb_e_enc = NE / TILEN;             // 5000
    const int nb_e = NE / TILE;                  // 2500

    // node encoder fused with layer-0 P/Q (+agg zero)
    encoder_kernel<30,32><<<nb_n, NTN, SMEM_NODE>>>(x, ne_w1, ne_b1, ne_a, ne_w2, ne_b2,
                                                    p_h, NN, le_w1);
    encoder_kernel<4,4>  <<<nb_e_enc, NTN, SMEM_NODE>>>(edge_attr, ee_w1, ee_b1, ee_a, ee_w2, ee_b2,
                                                        p_e, NE, (const float*)0);

    for (int l = 0; l < NLAYERS; ++l) {
        const float* wl = le_w1 + (size_t)l * 384 * LDIM;
        edge_kernel<<<nb_e, NT, SMEM_EDGEK>>>(edge_index, wl,
                                              le_b1 + l * LDIM, le_a + l,
                                              le_w2 + (size_t)l * LDIM * LDIM,
                                              le_b2 + l * LDIM);
        const float* wl_next = (l + 1 < NLAYERS) ? (le_w1 + (size_t)(l + 1) * 384 * LDIM)
                                                 : (const float*)0;
        node_kernel<<<nb_n, NTN, SMEM_NODE>>>(ln_w1 + (size_t)l * 256 * LDIM,
                                              ln_b1 + l * LDIM, ln_a + l,
                                              ln_w2 + (size_t)l * LDIM * LDIM,
                                              ln_b2 + l * LDIM,
                                              wl_next);
    }
    dec_kernel<<<nb_n, NTN, SMEM_NODE>>>(de_w1, de_b1, de_a, de_w2, de_b2, out);
}